// round 6
// baseline (speedup 1.0000x reference)
#include <cuda_runtime.h>
#include <stdint.h>

#define BB 4
#define HH 128
#define WW 128
#define CC 1024
#define NB 8
#define BS 128
#define HID 256
#define LAM 0.01f
#define NTOT (BB*HH*WW*CC)

// ---------------- scratch (device .bss, no allocation) ----------------
__device__ __align__(128) float g_buf1[NTOT];
__device__ __align__(128) float g_buf2[NTOT];
// cas matrix in mma A-fragment layout (raw fp32 bits; HMMA.tf32 truncates):
// frag t = (mt*16 + ks)*32 + lane ; 4 regs each
__device__ __align__(16) uint32_t g_casP[8*16*32*4];
__device__ __align__(16) uint32_t g_w1s[NB*BS*HID];   // folded [blk][i=128][o=256]
__device__ __align__(16) uint32_t g_w2s[NB*HID*BS];   // folded [blk][o=256][i=128]
__device__ float g_b1s[NB*HID];
__device__ float g_b2s[NB*BS];

// ---------------- helpers ----------------
__device__ __forceinline__ void mma8(float* c, uint32_t a0, uint32_t a1, uint32_t a2, uint32_t a3,
                                     uint32_t b0, uint32_t b1) {
    asm volatile("mma.sync.aligned.m16n8k8.row.col.f32.tf32.tf32.f32 "
                 "{%0,%1,%2,%3}, {%4,%5,%6,%7}, {%8,%9}, {%0,%1,%2,%3};"
                 : "+f"(c[0]), "+f"(c[1]), "+f"(c[2]), "+f"(c[3])
                 : "r"(a0), "r"(a1), "r"(a2), "r"(a3), "r"(b0), "r"(b1));
}
__device__ __forceinline__ void cp16(uint32_t saddr, const void* gptr) {
    asm volatile("cp.async.cg.shared.global [%0], [%1], 16;" :: "r"(saddr), "l"(gptr));
}
#define CP_COMMIT() asm volatile("cp.async.commit_group;")
#define CP_WAIT1()  asm volatile("cp.async.wait_group 1;")
#define CP_WAIT0()  asm volatile("cp.async.wait_group 0;")
__device__ __forceinline__ uint32_t sptr(const void* p) {
    return (uint32_t)__cvta_generic_to_shared(p);
}
__device__ __forceinline__ float sthr(float z) {
    return (z > LAM) ? (z - LAM) : ((z < -LAM) ? (z + LAM) : 0.f);
}

// ---------------- prep ----------------
__device__ __forceinline__ float casv(int m, int k) {
    float s, c;
    sincospif((float)((m * k) & 127) * (1.0f/64.0f), &s, &c);
    return c + s;
}

__global__ void prep_kernel(const float* __restrict__ w1, const float* __restrict__ b1,
                            const float* __restrict__ w2, const float* __restrict__ b2) {
    int t = blockIdx.x * blockDim.x + threadIdx.x;
    if (t < 8*16*32) {
        int lane = t & 31, ks = (t >> 5) & 15, mt = t >> 9;
        int g = lane >> 2, kk = ks*8 + (lane & 3);
        int m0 = mt*16 + g;
        uint32_t* d = &g_casP[t*4];
        d[0] = __float_as_uint(casv(m0,     kk));
        d[1] = __float_as_uint(casv(m0 + 8, kk));
        d[2] = __float_as_uint(casv(m0,     kk + 4));
        d[3] = __float_as_uint(casv(m0 + 8, kk + 4));
    }
    if (t < NB*BS*HID) {
        g_w1s[t] = __float_as_uint(w1[t] + w1[NB*BS*HID + t]);
        g_w2s[t] = __float_as_uint(w2[t] + w2[NB*HID*BS + t]);
    }
    if (t < NB*HID) g_b1s[t] = b1[t];
    if (t < NB*BS)  g_b2s[t] = b2[t];
}

// ---------------------------------------------------------------------------
// casmul_p: persistent W-direction transform (unchanged from round 3).
// OUT[bt, m, n] = scale * sum_k cas[m,k] IN[bt, k, n] (+add)
// ---------------------------------------------------------------------------
extern __shared__ uint32_t smu[];

__global__ __launch_bounds__(256, 2)
void casmul_p(const float* __restrict__ in, float* __restrict__ out,
              const float* __restrict__ addsrc, float scale, int ncols, int total) {
    const int tid = threadIdx.x;
    const int w = tid >> 5, lane = tid & 31;
    const int g = lane >> 2, tig = lane & 3;
    const int ntn = ncols >> 6;

    uint4 A[16];
    {
        const uint4* gA = (const uint4*)g_casP;
        #pragma unroll
        for (int ks = 0; ks < 16; ks++)
            A[ks] = __ldg(&gA[(w*16 + ks)*32 + lane]);
    }

    uint32_t* bS0 = smu;
    uint32_t* bS1 = smu + 9216;

    int t = blockIdx.x;
    {
        int bt = t / ntn, nb = t - bt*ntn;
        const float* src = in + (size_t)bt * 128u * (size_t)ncols + nb*64;
        #pragma unroll
        for (int i = 0; i < 8; i++) {
            int idx = i*256 + tid;
            int k = idx >> 4, n4 = (idx & 15) << 2;
            cp16(sptr(&bS0[k*72 + n4]), src + (size_t)k * (size_t)ncols + n4);
        }
    }
    CP_COMMIT();

    int buf = 0;
    for (; t < total; t += gridDim.x) {
        int tn = t + gridDim.x;
        if (tn < total) {
            uint32_t* bN = buf ? bS0 : bS1;
            int bt = tn / ntn, nb = tn - bt*ntn;
            const float* src = in + (size_t)bt * 128u * (size_t)ncols + nb*64;
            #pragma unroll
            for (int i = 0; i < 8; i++) {
                int idx = i*256 + tid;
                int k = idx >> 4, n4 = (idx & 15) << 2;
                cp16(sptr(&bN[k*72 + n4]), src + (size_t)k * (size_t)ncols + n4);
            }
        }
        CP_COMMIT();
        CP_WAIT1();
        __syncthreads();

        const uint32_t* bS = buf ? bS1 : bS0;
        float acc[8][4];
        #pragma unroll
        for (int i = 0; i < 8; i++)
            #pragma unroll
            for (int j = 0; j < 4; j++) acc[i][j] = 0.f;

        #pragma unroll
        for (int ks = 0; ks < 16; ks++) {
            uint32_t b[8][2];
            #pragma unroll
            for (int nf = 0; nf < 8; nf++) {
                int n = nf*8 + g;
                b[nf][0] = bS[(ks*8 + tig    )*72 + n];
                b[nf][1] = bS[(ks*8 + tig + 4)*72 + n];
            }
            #pragma unroll
            for (int nf = 0; nf < 8; nf++)
                mma8(acc[nf], A[ks].x, A[ks].y, A[ks].z, A[ks].w, b[nf][0], b[nf][1]);
        }

        {
            int bt = t / ntn, nb = t - bt*ntn;
            const size_t base = (size_t)bt * 128u * (size_t)ncols + nb*64;
            #pragma unroll
            for (int nf = 0; nf < 8; nf++) {
                int col = nf*8 + tig*2;
                #pragma unroll
                for (int r = 0; r < 2; r++) {
                    int row = w*16 + g + r*8;
                    size_t o = base + (size_t)row * (size_t)ncols + col;
                    float2 v;
                    v.x = acc[nf][r*2 + 0] * scale;
                    v.y = acc[nf][r*2 + 1] * scale;
                    if (addsrc) { v.x += addsrc[o]; v.y += addsrc[o + 1]; }
                    *(float2*)&out[o] = v;
                }
            }
        }
        __syncthreads();
        buf ^= 1;
    }
}

// ---------------------------------------------------------------------------
// fused_mid: per CTA: fixed (b, wcol, blk). Tile [128 h][128 c].
//   T = cas @ X           (H-transform, in-place in buf)
//   for ch in 0..3: O1 = relu(T @ W1ch + b1); acc2 += O1 @ W2ch
//   O2 = softthresh(acc2 + b2)  -> buf
//   Z = cas @ O2          -> gmem
// 512 threads = 16 warps (4m x 4n). smem = 143360 B.
// buf pitch 136: conflict-free for both A-pattern (8g+tig) and B-pattern (8tig+g).
// ---------------------------------------------------------------------------
__global__ __launch_bounds__(512, 1)
void fused_mid(const float* __restrict__ in, float* __restrict__ out) {
    uint32_t* buf  = smu;                  // 128*136 = 17408
    uint32_t* O1ch = smu + 17408;          // 128*72  = 9216
    uint32_t* Wb   = smu + 17408 + 9216;   // 9216 (W1 chunk 128x72 / W2 chunk 64x136)

    const int tid  = threadIdx.x;
    const int bI   = blockIdx.x >> 7;
    const int wcol = blockIdx.x & 127;
    const int blk  = blockIdx.y;

    const size_t gbase = ((size_t)(bI*128)*128u + (size_t)wcol)*1024u + (size_t)blk*128u;
    // element (h, c) at gbase + h*131072 + c

    // ---- load X tile [128h][128c] ----
    #pragma unroll
    for (int i = 0; i < 8; i++) {
        int idx = i*512 + tid;             // 4096 uint4
        int h = idx >> 5, c4 = (idx & 31) << 2;
        cp16(sptr(&buf[h*136 + c4]), in + gbase + (size_t)h*131072u + c4);
    }
    CP_COMMIT(); CP_WAIT0(); __syncthreads();

    const int wid = tid >> 5, lane = tid & 31;
    const int g = lane >> 2, tig = lane & 3;
    const int mw = wid & 3, nw = wid >> 2;     // 4m x 4n
    const uint4* gA = (const uint4*)g_casP;

    // ================= Phase T: T = cas @ X (in place) =================
    {
        float acc[2][4][4];
        #pragma unroll
        for (int a = 0; a < 2; a++)
            #pragma unroll
            for (int b = 0; b < 4; b++)
                #pragma unroll
                for (int c = 0; c < 4; c++) acc[a][b][c] = 0.f;

        #pragma unroll
        for (int ks = 0; ks < 16; ks++) {
            uint4 A0 = __ldg(&gA[((mw*2 + 0)*16 + ks)*32 + lane]);
            uint4 A1 = __ldg(&gA[((mw*2 + 1)*16 + ks)*32 + lane]);
            uint32_t bb[4][2];
            #pragma unroll
            for (int nf = 0; nf < 4; nf++) {
                int n = nw*32 + nf*8 + g;
                bb[nf][0] = buf[(ks*8 + tig    )*136 + n];
                bb[nf][1] = buf[(ks*8 + tig + 4)*136 + n];
            }
            #pragma unroll
            for (int nf = 0; nf < 4; nf++) {
                mma8(acc[0][nf], A0.x, A0.y, A0.z, A0.w, bb[nf][0], bb[nf][1]);
                mma8(acc[1][nf], A1.x, A1.y, A1.z, A1.w, bb[nf][0], bb[nf][1]);
            }
        }
        __syncthreads();   // all reads of X done
        #pragma unroll
        for (int mf = 0; mf < 2; mf++)
            #pragma unroll
            for (int nf = 0; nf < 4; nf++) {
                int n = nw*32 + nf*8 + tig*2;
                #pragma unroll
                for (int r = 0; r < 2; r++) {
                    int m = mw*32 + mf*16 + g + r*8;
                    buf[m*136 + n    ] = __float_as_uint(acc[mf][nf][r*2 + 0]);
                    buf[m*136 + n + 1] = __float_as_uint(acc[mf][nf][r*2 + 1]);
                }
            }
        __syncthreads();   // T complete
    }

    // ================= MLP: 4 chunks of 64 hidden =================
    const uint32_t* W1 = g_w1s + blk*BS*HID;
    const uint32_t* W2 = g_w2s + blk*HID*BS;

    float acc2[2][4][4];
    #pragma unroll
    for (int a = 0; a < 2; a++)
        #pragma unroll
        for (int b = 0; b < 4; b++)
            #pragma unroll
            for (int c = 0; c < 4; c++) acc2[a][b][c] = 0.f;

    for (int ch = 0; ch < 4; ch++) {
        // ---- stage W1 chunk [128k][64n] pitch 72 ----
        #pragma unroll
        for (int i = 0; i < 4; i++) {
            int idx = i*512 + tid;          // 2048 uint4
            int k = idx >> 4, n4 = (idx & 15) << 2;
            cp16(sptr(&Wb[k*72 + n4]), W1 + k*HID + ch*64 + n4);
        }
        CP_COMMIT(); CP_WAIT0(); __syncthreads();

        // ---- GEMM1: [128,128]@[128,64], warp tile 32m x 16n ----
        float acc1[2][2][4];
        #pragma unroll
        for (int a = 0; a < 2; a++)
            #pragma unroll
            for (int b = 0; b < 2; b++)
                #pragma unroll
                for (int c = 0; c < 4; c++) acc1[a][b][c] = 0.f;

        #pragma unroll
        for (int ks = 0; ks < 16; ks++) {
            int kk = ks*8;
            uint32_t a[2][4];
            #pragma unroll
            for (int mf = 0; mf < 2; mf++) {
                int m = mw*32 + mf*16;
                a[mf][0] = buf[(m + g    )*136 + kk + tig    ];
                a[mf][1] = buf[(m + g + 8)*136 + kk + tig    ];
                a[mf][2] = buf[(m + g    )*136 + kk + tig + 4];
                a[mf][3] = buf[(m + g + 8)*136 + kk + tig + 4];
            }
            uint32_t bb[2][2];
            #pragma unroll
            for (int nf = 0; nf < 2; nf++) {
                int n = nw*16 + nf*8 + g;
                bb[nf][0] = Wb[(kk + tig    )*72 + n];
                bb[nf][1] = Wb[(kk + tig + 4)*72 + n];
            }
            #pragma unroll
            for (int mf = 0; mf < 2; mf++)
                #pragma unroll
                for (int nf = 0; nf < 2; nf++)
                    mma8(acc1[mf][nf], a[mf][0], a[mf][1], a[mf][2], a[mf][3], bb[nf][0], bb[nf][1]);
        }

        // ---- bias + relu -> O1ch [128][72] ----
        #pragma unroll
        for (int mf = 0; mf < 2; mf++)
            #pragma unroll
            for (int nf = 0; nf < 2; nf++) {
                int nc = nw*16 + nf*8 + tig*2;
                float bx = g_b1s[blk*HID + ch*64 + nc];
                float by = g_b1s[blk*HID + ch*64 + nc + 1];
                #pragma unroll
                for (int r = 0; r < 2; r++) {
                    int m = mw*32 + mf*16 + g + r*8;
                    O1ch[m*72 + nc    ] = __float_as_uint(fmaxf(acc1[mf][nf][r*2 + 0] + bx, 0.f));
                    O1ch[m*72 + nc + 1] = __float_as_uint(fmaxf(acc1[mf][nf][r*2 + 1] + by, 0.f));
                }
            }
        __syncthreads();   // O1ch ready; Wb reads done

        // ---- stage W2 chunk [64k][128n] pitch 136 ----
        #pragma unroll
        for (int i = 0; i < 4; i++) {
            int idx = i*512 + tid;          // 2048 uint4
            int k = idx >> 5, n4 = (idx & 31) << 2;
            cp16(sptr(&Wb[k*136 + n4]), W2 + (ch*64 + k)*BS + n4);
        }
        CP_COMMIT(); CP_WAIT0(); __syncthreads();

        // ---- GEMM2 partial: [128,64]@[64,128], warp tile 32m x 32n ----
        #pragma unroll
        for (int ks = 0; ks < 8; ks++) {
            int kk = ks*8;
            uint32_t a[2][4];
            #pragma unroll
            for (int mf = 0; mf < 2; mf++) {
                int m = mw*32 + mf*16;
                a[mf][0] = O1ch[(m + g    )*72 + kk + tig    ];
                a[mf][1] = O1ch[(m + g + 8)*72 + kk + tig    ];
                a[mf][2] = O1ch[(m + g    )*72 + kk + tig + 4];
                a[mf][3] = O1ch[(m + g + 8)*72 + kk + tig + 4];
            }
            uint32_t bb[4][2];
            #pragma unroll
            for (int nf = 0; nf < 4; nf++) {
                int n = nw*32 + nf*8 + g;
                bb[nf][0] = Wb[(kk + tig    )*136 + n];
                bb[nf][1] = Wb[(kk + tig + 4)*136 + n];
            }
            #pragma unroll
            for (int mf = 0; mf < 2; mf++)
                #pragma unroll
                for (int nf = 0; nf < 4; nf++)
                    mma8(acc2[mf][nf], a[mf][0], a[mf][1], a[mf][2], a[mf][3], bb[nf][0], bb[nf][1]);
        }
        __syncthreads();   // Wb/O1ch reads done before next chunk restage
    }

    // ---- O2 = softthresh(acc2 + b2) -> buf ----
    #pragma unroll
    for (int mf = 0; mf < 2; mf++)
        #pragma unroll
        for (int nf = 0; nf < 4; nf++) {
            int n = nw*32 + nf*8 + tig*2;
            float bx = g_b2s[blk*BS + n];
            float by = g_b2s[blk*BS + n + 1];
            #pragma unroll
            for (int r = 0; r < 2; r++) {
                int m = mw*32 + mf*16 + g + r*8;
                buf[m*136 + n    ] = __float_as_uint(sthr(acc2[mf][nf][r*2 + 0] + bx));
                buf[m*136 + n + 1] = __float_as_uint(sthr(acc2[mf][nf][r*2 + 1] + by));
            }
        }
    __syncthreads();

    // ================= Phase Z: Z = cas @ O2 -> gmem =================
    {
        float acc[2][4][4];
        #pragma unroll
        for (int a = 0; a < 2; a++)
            #pragma unroll
            for (int b = 0; b < 4; b++)
                #pragma unroll
                for (int c = 0; c < 4; c++) acc[a][b][c] = 0.f;

        #pragma unroll
        for (int ks = 0; ks < 16; ks++) {
            uint4 A0 = __ldg(&gA[((mw*2 + 0)*16 + ks)*32 + lane]);
            uint4 A1 = __ldg(&gA[((mw*2 + 1)*16 + ks)*32 + lane]);
            uint32_t bb[4][2];
            #pragma unroll
            for (int nf = 0; nf < 4; nf++) {
                int n = nw*32 + nf*8 + g;
                bb[nf][0] = buf[(ks*8 + tig    )*136 + n];
                bb[nf][1] = buf[(ks*8 + tig + 4)*136 + n];
            }
            #pragma unroll
            for (int nf = 0; nf < 4; nf++) {
                mma8(acc[0][nf], A0.x, A0.y, A0.z, A0.w, bb[nf][0], bb[nf][1]);
                mma8(acc[1][nf], A1.x, A1.y, A1.z, A1.w, bb[nf][0], bb[nf][1]);
            }
        }

        #pragma unroll
        for (int mf = 0; mf < 2; mf++)
            #pragma unroll
            for (int nf = 0; nf < 4; nf++) {
                int n = nw*32 + nf*8 + tig*2;
                #pragma unroll
                for (int r = 0; r < 2; r++) {
                    int m = mw*32 + mf*16 + g + r*8;
                    float2 v;
                    v.x = acc[mf][nf][r*2 + 0];
                    v.y = acc[mf][nf][r*2 + 1];
                    *(float2*)&out[gbase + (size_t)m*131072u + n] = v;
                }
            }
    }
}

// ---------------------------------------------------------------------------
extern "C" void kernel_launch(void* const* d_in, const int* in_sizes, int n_in,
                              void* d_out, int out_size) {
    const float* x  = (const float*)d_in[0];
    const float* w1 = (const float*)d_in[1];
    const float* b1 = (const float*)d_in[2];
    const float* w2 = (const float*)d_in[3];
    const float* b2 = (const float*)d_in[4];
    float* out = (float*)d_out;

    void *p1, *p2;
    cudaGetSymbolAddress(&p1, g_buf1);
    cudaGetSymbolAddress(&p2, g_buf2);
    float* buf1 = (float*)p1;
    float* buf2 = (float*)p2;

    const int CAS_SMEM = 2 * 128 * 72 * 4;              // 73728
    const int MID_SMEM = (17408 + 9216 + 9216) * 4;     // 143360
    cudaFuncSetAttribute(casmul_p,  cudaFuncAttributeMaxDynamicSharedMemorySize, CAS_SMEM);
    cudaFuncSetAttribute(fused_mid, cudaFuncAttributeMaxDynamicSharedMemorySize, MID_SMEM);

    prep_kernel<<<1024, 256>>>(w1, b1, w2, b2);

    const int GRID = 296;
    const int T1 = (CC/64) * (BB*HH);      // 8192 tiles (W-direction)

    // pass 1: forward transform along W
    casmul_p<<<GRID, 256, CAS_SMEM>>>(x, buf1, nullptr, 1.0f, CC, T1);

    // fused: H-transform + block MLP + soft-threshold + inverse H-transform
    fused_mid<<<dim3(BB*WW, NB), 512, MID_SMEM>>>(buf1, buf2);

    // pass 5: inverse transform along W, scale 1/(H*W), add residual
    casmul_p<<<GRID, 256, CAS_SMEM>>>(buf2, out, x, 1.0f/(HH*WW), CC, T1);
}

// round 7
// speedup vs baseline: 1.9451x; 1.9451x over previous
#include <cuda_runtime.h>
#include <cuda_fp16.h>
#include <stdint.h>

#define BB 4
#define HH 128
#define WW 128
#define CC 1024
#define NB 8
#define BS 128
#define HID 256
#define LAM 0.01f
#define NTOT (BB*HH*WW*CC)

// ---------------- scratch (device .bss, no allocation) ----------------
__device__ __align__(128) float g_buf1[NTOT];
__device__ __align__(128) float g_buf2[NTOT];
// cas matrix packed as m16n8k16 A-fragments (half2 in each u32):
// index (mt*8 + ks)*32 + lane -> uint4 {a0,a1,a2,a3}
__device__ __align__(16) uint4 g_casPH[8*8*32];
__device__ __align__(16) __half g_w1h[NB*BS*HID];   // folded [blk][i=128][o=256]
__device__ __align__(16) __half g_w2h[NB*HID*BS];   // folded [blk][o=256][i=128]
__device__ float g_b1s[NB*HID];
__device__ float g_b2s[NB*BS];

// ---------------- helpers ----------------
__device__ __forceinline__ void mma16(float* c, uint32_t a0, uint32_t a1, uint32_t a2, uint32_t a3,
                                      uint32_t b0, uint32_t b1) {
    asm volatile("mma.sync.aligned.m16n8k16.row.col.f32.f16.f16.f32 "
                 "{%0,%1,%2,%3}, {%4,%5,%6,%7}, {%8,%9}, {%0,%1,%2,%3};"
                 : "+f"(c[0]), "+f"(c[1]), "+f"(c[2]), "+f"(c[3])
                 : "r"(a0), "r"(a1), "r"(a2), "r"(a3), "r"(b0), "r"(b1));
}
__device__ __forceinline__ void ldsm4(uint32_t* r, uint32_t a) {
    asm volatile("ldmatrix.sync.aligned.m8n8.x4.shared.b16 {%0,%1,%2,%3}, [%4];"
                 : "=r"(r[0]), "=r"(r[1]), "=r"(r[2]), "=r"(r[3]) : "r"(a));
}
__device__ __forceinline__ void ldsm4t(uint32_t* r, uint32_t a) {
    asm volatile("ldmatrix.sync.aligned.m8n8.x4.trans.shared.b16 {%0,%1,%2,%3}, [%4];"
                 : "=r"(r[0]), "=r"(r[1]), "=r"(r[2]), "=r"(r[3]) : "r"(a));
}
__device__ __forceinline__ void cp16(uint32_t saddr, const void* gptr) {
    asm volatile("cp.async.cg.shared.global [%0], [%1], 16;" :: "r"(saddr), "l"(gptr));
}
#define CP_COMMIT() asm volatile("cp.async.commit_group;")
#define CP_WAIT0()  asm volatile("cp.async.wait_group 0;")
__device__ __forceinline__ uint32_t sptr(const void* p) {
    return (uint32_t)__cvta_generic_to_shared(p);
}
__device__ __forceinline__ uint32_t pack2(float a, float b) {
    __half2 h = __floats2half2_rn(a, b);
    return *reinterpret_cast<uint32_t*>(&h);
}
__device__ __forceinline__ float sthr(float z) {
    return (z > LAM) ? (z - LAM) : ((z < -LAM) ? (z + LAM) : 0.f);
}

// ---------------- prep ----------------
__device__ __forceinline__ float casv(int m, int k) {
    float s, c;
    sincospif((float)((m * k) & 127) * (1.0f/64.0f), &s, &c);
    return c + s;
}

__global__ void prep_kernel(const float* __restrict__ w1, const float* __restrict__ b1,
                            const float* __restrict__ w2, const float* __restrict__ b2) {
    int t = blockIdx.x * blockDim.x + threadIdx.x;
    if (t < 8*8*32) {
        int lane = t & 31, ks = (t >> 5) & 7, mt = t >> 8;
        int g = lane >> 2, tig = lane & 3;
        int m0 = mt*16 + g, k0 = ks*16 + 2*tig;
        uint4 v;
        v.x = pack2(casv(m0,     k0),     casv(m0,     k0 + 1));
        v.y = pack2(casv(m0 + 8, k0),     casv(m0 + 8, k0 + 1));
        v.z = pack2(casv(m0,     k0 + 8), casv(m0,     k0 + 9));
        v.w = pack2(casv(m0 + 8, k0 + 8), casv(m0 + 8, k0 + 9));
        g_casPH[t] = v;
    }
    if (t < NB*BS*HID) {
        g_w1h[t] = __float2half(w1[t] + w1[NB*BS*HID + t]);
        g_w2h[t] = __float2half(w2[t] + w2[NB*HID*BS + t]);
    }
    if (t < NB*HID) g_b1s[t] = b1[t];
    if (t < NB*BS)  g_b2s[t] = b2[t];
}

// ---------------------------------------------------------------------------
// casmul_h: persistent. OUT[bt,m,n] = scale * sum_k cas[m,k] IN[bt,k,n] (+add)
// Tile 128m x 64n x 128k. 8 warps; warp w owns rows [16w,16w+16) (cas A in regs).
// B tile staged as half [128k][72 pitch]; register-prefetch of next tile.
// smem = 18432 B -> 2 CTAs/SM.
// ---------------------------------------------------------------------------
extern __shared__ uint32_t smu[];

__global__ __launch_bounds__(256, 2)
void casmul_h(const float* __restrict__ in, float* __restrict__ out,
              const float* __restrict__ addsrc, float scale, int ncols, int total) {
    char* bS = (char*)smu;                 // half [128][72] via byte addressing
    const int tid = threadIdx.x;
    const int w = tid >> 5, lane = tid & 31;
    const int g = lane >> 2, tig = lane & 3;
    const int l15 = lane & 15, lc8 = (lane >> 4) * 8;
    const int ntn = ncols >> 6;

    uint4 A[8];
    #pragma unroll
    for (int ks = 0; ks < 8; ks++)
        A[ks] = __ldg(&g_casPH[(w*8 + ks)*32 + lane]);

    float4 pf[8];
    int t = blockIdx.x;
    {
        int bt = t / ntn, nb = t - bt*ntn;
        const float* src = in + (size_t)bt * 128u * (size_t)ncols + nb*64;
        #pragma unroll
        for (int i = 0; i < 8; i++) {
            int idx = i*256 + tid;
            int k = idx >> 4, n4 = (idx & 15) << 2;
            pf[i] = *(const float4*)(src + (size_t)k * (size_t)ncols + n4);
        }
    }

    for (; t < total; t += gridDim.x) {
        __syncthreads();   // prior tile's MMA reads done
        #pragma unroll
        for (int i = 0; i < 8; i++) {
            int idx = i*256 + tid;
            int k = idx >> 4, n4 = (idx & 15) << 2;
            uint2 u;
            u.x = pack2(pf[i].x, pf[i].y);
            u.y = pack2(pf[i].z, pf[i].w);
            *(uint2*)(bS + k*144 + n4*2) = u;
        }
        __syncthreads();

        int tn = t + gridDim.x;
        if (tn < total) {   // prefetch next tile (LDG overlaps MMA below)
            int bt = tn / ntn, nb = tn - bt*ntn;
            const float* src = in + (size_t)bt * 128u * (size_t)ncols + nb*64;
            #pragma unroll
            for (int i = 0; i < 8; i++) {
                int idx = i*256 + tid;
                int k = idx >> 4, n4 = (idx & 15) << 2;
                pf[i] = *(const float4*)(src + (size_t)k * (size_t)ncols + n4);
            }
        }

        float acc[8][4];
        #pragma unroll
        for (int i = 0; i < 8; i++)
            #pragma unroll
            for (int j = 0; j < 4; j++) acc[i][j] = 0.f;

        #pragma unroll
        for (int ks = 0; ks < 8; ks++) {
            #pragma unroll
            for (int nq = 0; nq < 4; nq++) {
                uint32_t b[4];
                ldsm4t(b, sptr(bS + (ks*16 + l15)*144 + (nq*16 + lc8)*2));
                mma16(acc[nq*2    ], A[ks].x, A[ks].y, A[ks].z, A[ks].w, b[0], b[1]);
                mma16(acc[nq*2 + 1], A[ks].x, A[ks].y, A[ks].z, A[ks].w, b[2], b[3]);
            }
        }

        {
            int bt = t / ntn, nb = t - bt*ntn;
            const size_t base = (size_t)bt * 128u * (size_t)ncols + nb*64;
            #pragma unroll
            for (int nf = 0; nf < 8; nf++) {
                int col = nf*8 + tig*2;
                #pragma unroll
                for (int r = 0; r < 2; r++) {
                    int row = w*16 + g + r*8;
                    size_t o = base + (size_t)row * (size_t)ncols + col;
                    float2 v;
                    v.x = acc[nf][r*2 + 0] * scale;
                    v.y = acc[nf][r*2 + 1] * scale;
                    if (addsrc) { v.x += addsrc[o]; v.y += addsrc[o + 1]; }
                    *(float2*)&out[o] = v;
                }
            }
        }
    }
}

// ---------------------------------------------------------------------------
// fused_h: per CTA (b, wcol, blk): tile [128h][128c], all fp16 operands.
//   T = cas @ X; MLP(4 chunks of 64 hidden); O2 = softthresh; Z = cas @ O2.
// 256 threads = 8 warps (4m x 2n). smem = 89088 B -> 2 CTAs/SM.
// ---------------------------------------------------------------------------
__global__ __launch_bounds__(256, 2)
void fused_h(const float* __restrict__ in, float* __restrict__ out) {
    char* buf = (char*)smu;                  // half [128][136] = 34816 B
    char* O1  = buf + 34816;                 // half [128][72]  = 18432 B
    char* Wb1 = O1 + 18432;                  // half [128][72]  = 18432 B
    char* Wb2 = Wb1 + 18432;                 // half [64][136]  = 17408 B

    const int tid  = threadIdx.x;
    const int bI   = blockIdx.x >> 7;
    const int wcol = blockIdx.x & 127;
    const int blk  = blockIdx.y;
    const size_t gbase = ((size_t)(bI*128)*128u + (size_t)wcol)*1024u + (size_t)blk*128u;

    // ---- load X tile [128h][128c] -> half ----
    #pragma unroll
    for (int i = 0; i < 16; i++) {
        int idx = i*256 + tid;
        int h = idx >> 5, c4 = (idx & 31) << 2;
        float4 v = *(const float4*)(in + gbase + (size_t)h*131072u + c4);
        uint2 u;
        u.x = pack2(v.x, v.y);
        u.y = pack2(v.z, v.w);
        *(uint2*)(buf + h*272 + c4*2) = u;
    }

    const int wid = tid >> 5, lane = tid & 31;
    const int g = lane >> 2, tig = lane & 3;
    const int mw = wid & 3, nw = wid >> 2;   // 4m x 2n
    const int l15 = lane & 15, lc8 = (lane >> 4) * 8;
    const int m0 = mw*32;
    __syncthreads();

    // ================= Phase T: T = cas @ X =================
    {
        float acc[2][8][4];
        #pragma unroll
        for (int a = 0; a < 2; a++)
            #pragma unroll
            for (int b = 0; b < 8; b++)
                #pragma unroll
                for (int c = 0; c < 4; c++) acc[a][b][c] = 0.f;

        #pragma unroll
        for (int ks = 0; ks < 8; ks++) {
            uint4 A0 = __ldg(&g_casPH[((mw*2    )*8 + ks)*32 + lane]);
            uint4 A1 = __ldg(&g_casPH[((mw*2 + 1)*8 + ks)*32 + lane]);
            #pragma unroll
            for (int nq = 0; nq < 4; nq++) {
                uint32_t b[4];
                ldsm4t(b, sptr(buf + (ks*16 + l15)*272 + (nw*64 + nq*16 + lc8)*2));
                mma16(acc[0][nq*2    ], A0.x, A0.y, A0.z, A0.w, b[0], b[1]);
                mma16(acc[0][nq*2 + 1], A0.x, A0.y, A0.z, A0.w, b[2], b[3]);
                mma16(acc[1][nq*2    ], A1.x, A1.y, A1.z, A1.w, b[0], b[1]);
                mma16(acc[1][nq*2 + 1], A1.x, A1.y, A1.z, A1.w, b[2], b[3]);
            }
        }
        __syncthreads();   // all X reads done before overwrite
        #pragma unroll
        for (int mf = 0; mf < 2; mf++)
            #pragma unroll
            for (int nf = 0; nf < 8; nf++) {
                int n = nw*64 + nf*8 + tig*2;
                #pragma unroll
                for (int r = 0; r < 2; r++) {
                    int m = m0 + mf*16 + g + r*8;
                    *(uint32_t*)(buf + m*272 + n*2) =
                        pack2(acc[mf][nf][r*2 + 0], acc[mf][nf][r*2 + 1]);
                }
            }
        __syncthreads();   // T complete
    }

    // ================= MLP: 4 chunks of 64 hidden =================
    const __half* W1 = g_w1h + blk*BS*HID;
    const __half* W2 = g_w2h + blk*HID*BS;

    float acc2[2][8][4];
    #pragma unroll
    for (int a = 0; a < 2; a++)
        #pragma unroll
        for (int b = 0; b < 8; b++)
            #pragma unroll
            for (int c = 0; c < 4; c++) acc2[a][b][c] = 0.f;

    for (int ch = 0; ch < 4; ch++) {
        // stage W1 chunk [128k][64n] pitch 72 + W2 chunk [64k][128n] pitch 136
        #pragma unroll
        for (int i = 0; i < 4; i++) {
            int idx = i*256 + tid;
            int k = idx >> 3, seg = idx & 7;
            cp16(sptr(Wb1 + k*144 + seg*16), W1 + k*HID + ch*64 + seg*8);
        }
        #pragma unroll
        for (int i = 0; i < 4; i++) {
            int idx = i*256 + tid;
            int k = idx >> 4, seg = idx & 15;
            cp16(sptr(Wb2 + k*272 + seg*16), W2 + (size_t)(ch*64 + k)*BS + seg*8);
        }
        CP_COMMIT(); CP_WAIT0(); __syncthreads();

        // ---- GEMM1: [128,128]@[128,64], warp n-range 32 ----
        float acc1[2][4][4];
        #pragma unroll
        for (int a = 0; a < 2; a++)
            #pragma unroll
            for (int b = 0; b < 4; b++)
                #pragma unroll
                for (int c = 0; c < 4; c++) acc1[a][b][c] = 0.f;

        #pragma unroll
        for (int ks = 0; ks < 8; ks++) {
            uint32_t a0[4], a1[4];
            ldsm4(a0, sptr(buf + (m0      + l15)*272 + (ks*16 + lc8)*2));
            ldsm4(a1, sptr(buf + (m0 + 16 + l15)*272 + (ks*16 + lc8)*2));
            #pragma unroll
            for (int nq = 0; nq < 2; nq++) {
                uint32_t b[4];
                ldsm4t(b, sptr(Wb1 + (ks*16 + l15)*144 + (nw*32 + nq*16 + lc8)*2));
                mma16(acc1[0][nq*2    ], a0[0], a0[1], a0[2], a0[3], b[0], b[1]);
                mma16(acc1[0][nq*2 + 1], a0[0], a0[1], a0[2], a0[3], b[2], b[3]);
                mma16(acc1[1][nq*2    ], a1[0], a1[1], a1[2], a1[3], b[0], b[1]);
                mma16(acc1[1][nq*2 + 1], a1[0], a1[1], a1[2], a1[3], b[2], b[3]);
            }
        }

        // ---- bias + relu -> O1 [128][64] pitch 72 ----
        #pragma unroll
        for (int mf = 0; mf < 2; mf++)
            #pragma unroll
            for (int nf = 0; nf < 4; nf++) {
                int nc = nw*32 + nf*8 + tig*2;
                float bx = g_b1s[blk*HID + ch*64 + nc];
                float by = g_b1s[blk*HID + ch*64 + nc + 1];
                #pragma unroll
                for (int r = 0; r < 2; r++) {
                    int m = m0 + mf*16 + g + r*8;
                    *(uint32_t*)(O1 + m*144 + nc*2) =
                        pack2(fmaxf(acc1[mf][nf][r*2 + 0] + bx, 0.f),
                              fmaxf(acc1[mf][nf][r*2 + 1] + by, 0.f));
                }
            }
        __syncthreads();   // O1 complete

        // ---- GEMM2 partial: [128,64]@[64,128], warp n-range 64 ----
        #pragma unroll
        for (int ks = 0; ks < 4; ks++) {
            uint32_t a0[4], a1[4];
            ldsm4(a0, sptr(O1 + (m0      + l15)*144 + (ks*16 + lc8)*2));
            ldsm4(a1, sptr(O1 + (m0 + 16 + l15)*144 + (ks*16 + lc8)*2));
            #pragma unroll
            for (int nq = 0; nq < 4; nq++) {
                uint32_t b[4];
                ldsm4t(b, sptr(Wb2 + (ks*16 + l15)*272 + (nw*64 + nq*16 + lc8)*2));
                mma16(acc2[0][nq*2    ], a0[0], a0[1], a0[2], a0[3], b[0], b[1]);
                mma16(acc2[0][nq*2 + 1], a0[0], a0[1], a0[2], a0[3], b[2], b[3]);
                mma16(acc2[1][nq*2    ], a1[0], a1[1], a1[2], a1[3], b[0], b[1]);
                mma16(acc2[1][nq*2 + 1], a1[0], a1[1], a1[2], a1[3], b[2], b[3]);
            }
        }
        __syncthreads();   // Wb/O1 reads done before next chunk restage
    }

    // ---- O2 = softthresh(acc2 + b2) -> buf ----
    #pragma unroll
    for (int mf = 0; mf < 2; mf++)
        #pragma unroll
        for (int nf = 0; nf < 8; nf++) {
            int n = nw*64 + nf*8 + tig*2;
            float bx = g_b2s[blk*BS + n];
            float by = g_b2s[blk*BS + n + 1];
            #pragma unroll
            for (int r = 0; r < 2; r++) {
                int m = m0 + mf*16 + g + r*8;
                *(uint32_t*)(buf + m*272 + n*2) =
                    pack2(sthr(acc2[mf][nf][r*2 + 0] + bx),
                          sthr(acc2[mf][nf][r*2 + 1] + by));
            }
        }
    __syncthreads();

    // ================= Phase Z: Z = cas @ O2 -> gmem =================
    {
        float acc[2][8][4];
        #pragma unroll
        for (int a = 0; a < 2; a++)
            #pragma unroll
            for (int b = 0; b < 8; b++)
                #pragma unroll
                for (int c = 0; c < 4; c++) acc[a][b][c] = 0.f;

        #pragma unroll
        for (int ks = 0; ks < 8; ks++) {
            uint4 A0 = __ldg(&g_casPH[((mw*2    )*8 + ks)*32 + lane]);
            uint4 A1 = __ldg(&g_casPH[((mw*2 + 1)*8 + ks)*32 + lane]);
            #pragma unroll
            for (int nq = 0; nq < 4; nq++) {
                uint32_t b[4];
                ldsm4t(b, sptr(buf + (ks*16 + l15)*272 + (nw*64 + nq*16 + lc8)*2));
                mma16(acc[0][nq*2    ], A0.x, A0.y, A0.z, A0.w, b[0], b[1]);
                mma16(acc[0][nq*2 + 1], A0.x, A0.y, A0.z, A0.w, b[2], b[3]);
                mma16(acc[1][nq*2    ], A1.x, A1.y, A1.z, A1.w, b[0], b[1]);
                mma16(acc[1][nq*2 + 1], A1.x, A1.y, A1.z, A1.w, b[2], b[3]);
            }
        }

        #pragma unroll
        for (int mf = 0; mf < 2; mf++)
            #pragma unroll
            for (int nf = 0; nf < 8; nf++) {
                int n = nw*64 + nf*8 + tig*2;
                #pragma unroll
                for (int r = 0; r < 2; r++) {
                    int m = m0 + mf*16 + g + r*8;
                    float2 v;
                    v.x = acc[mf][nf][r*2 + 0];
                    v.y = acc[mf][nf][r*2 + 1];
                    *(float2*)&out[gbase + (size_t)m*131072u + n] = v;
                }
            }
    }
}

// ---------------------------------------------------------------------------
extern "C" void kernel_launch(void* const* d_in, const int* in_sizes, int n_in,
                              void* d_out, int out_size) {
    const float* x  = (const float*)d_in[0];
    const float* w1 = (const float*)d_in[1];
    const float* b1 = (const float*)d_in[2];
    const float* w2 = (const float*)d_in[3];
    const float* b2 = (const float*)d_in[4];
    float* out = (float*)d_out;

    void *p1, *p2;
    cudaGetSymbolAddress(&p1, g_buf1);
    cudaGetSymbolAddress(&p2, g_buf2);
    float* buf1 = (float*)p1;
    float* buf2 = (float*)p2;

    const int CAS_SMEM = 128 * 72 * 2;                       // 18432
    const int MID_SMEM = 34816 + 18432 + 18432 + 17408;      // 89088
    cudaFuncSetAttribute(casmul_h, cudaFuncAttributeMaxDynamicSharedMemorySize, CAS_SMEM);
    cudaFuncSetAttribute(fused_h,  cudaFuncAttributeMaxDynamicSharedMemorySize, MID_SMEM);

    prep_kernel<<<1024, 256>>>(w1, b1, w2, b2);

    const int GRID = 296;
    const int T1 = (CC/64) * (BB*HH);      // 8192 tiles (W-direction)

    // pass 1: forward transform along W
    casmul_h<<<GRID, 256, CAS_SMEM>>>(x, buf1, nullptr, 1.0f, CC, T1);

    // fused: H-transform + block MLP + soft-threshold + inverse H-transform
    fused_h<<<dim3(BB*WW, NB), 256, MID_SMEM>>>(buf1, buf2);

    // pass 5: inverse transform along W, scale 1/(H*W), add residual
    casmul_h<<<GRID, 256, CAS_SMEM>>>(buf2, out, x, 1.0f/(HH*WW), CC, T1);
}

// round 8
// speedup vs baseline: 2.1189x; 1.0894x over previous
#include <cuda_runtime.h>
#include <cuda_fp16.h>
#include <stdint.h>

#define BB 4
#define HH 128
#define WW 128
#define CC 1024
#define NB 8
#define BS 128
#define HID 256
#define LAM 0.01f
#define NTOT (BB*HH*WW*CC)

// ---------------- scratch (device .bss, no allocation) ----------------
// fp16 intermediates overlay the big buffers
__device__ __align__(128) __half g_bh1[NTOT];
__device__ __align__(128) __half g_bh2[NTOT];
// cas matrix packed as m16n8k16 A-fragments (half2 in each u32):
// index (mt*8 + ks)*32 + lane -> uint4 {a0,a1,a2,a3}
__device__ __align__(16) uint4 g_casPH[8*8*32];
__device__ __align__(16) __half g_w1h[NB*BS*HID];   // folded [blk][i=128][o=256]
__device__ __align__(16) __half g_w2h[NB*HID*BS];   // folded [blk][o=256][i=128]
__device__ float g_b1s[NB*HID];
__device__ float g_b2s[NB*BS];

// ---------------- helpers ----------------
__device__ __forceinline__ void mma16(float* c, uint32_t a0, uint32_t a1, uint32_t a2, uint32_t a3,
                                      uint32_t b0, uint32_t b1) {
    asm volatile("mma.sync.aligned.m16n8k16.row.col.f32.f16.f16.f32 "
                 "{%0,%1,%2,%3}, {%4,%5,%6,%7}, {%8,%9}, {%0,%1,%2,%3};"
                 : "+f"(c[0]), "+f"(c[1]), "+f"(c[2]), "+f"(c[3])
                 : "r"(a0), "r"(a1), "r"(a2), "r"(a3), "r"(b0), "r"(b1));
}
__device__ __forceinline__ void ldsm4(uint32_t* r, uint32_t a) {
    asm volatile("ldmatrix.sync.aligned.m8n8.x4.shared.b16 {%0,%1,%2,%3}, [%4];"
                 : "=r"(r[0]), "=r"(r[1]), "=r"(r[2]), "=r"(r[3]) : "r"(a));
}
__device__ __forceinline__ void ldsm4t(uint32_t* r, uint32_t a) {
    asm volatile("ldmatrix.sync.aligned.m8n8.x4.trans.shared.b16 {%0,%1,%2,%3}, [%4];"
                 : "=r"(r[0]), "=r"(r[1]), "=r"(r[2]), "=r"(r[3]) : "r"(a));
}
__device__ __forceinline__ void cp16(uint32_t saddr, const void* gptr) {
    asm volatile("cp.async.cg.shared.global [%0], [%1], 16;" :: "r"(saddr), "l"(gptr));
}
#define CP_COMMIT() asm volatile("cp.async.commit_group;")
#define CP_WAIT1()  asm volatile("cp.async.wait_group 1;")
#define CP_WAIT0()  asm volatile("cp.async.wait_group 0;")
__device__ __forceinline__ uint32_t sptr(const void* p) {
    return (uint32_t)__cvta_generic_to_shared(p);
}
__device__ __forceinline__ uint32_t pack2(float a, float b) {
    __half2 h = __floats2half2_rn(a, b);
    return *reinterpret_cast<uint32_t*>(&h);
}
__device__ __forceinline__ float sthr(float z) {
    return (z > LAM) ? (z - LAM) : ((z < -LAM) ? (z + LAM) : 0.f);
}

// ---------------- prep ----------------
__device__ __forceinline__ float casv(int m, int k) {
    float s, c;
    sincospif((float)((m * k) & 127) * (1.0f/64.0f), &s, &c);
    return c + s;
}

__global__ void prep_kernel(const float* __restrict__ w1, const float* __restrict__ b1,
                            const float* __restrict__ w2, const float* __restrict__ b2) {
    int t = blockIdx.x * blockDim.x + threadIdx.x;
    if (t < 8*8*32) {
        int lane = t & 31, ks = (t >> 5) & 7, mt = t >> 8;
        int g = lane >> 2, tig = lane & 3;
        int m0 = mt*16 + g, k0 = ks*16 + 2*tig;
        uint4 v;
        v.x = pack2(casv(m0,     k0),     casv(m0,     k0 + 1));
        v.y = pack2(casv(m0 + 8, k0),     casv(m0 + 8, k0 + 1));
        v.z = pack2(casv(m0,     k0 + 8), casv(m0,     k0 + 9));
        v.w = pack2(casv(m0 + 8, k0 + 8), casv(m0 + 8, k0 + 9));
        g_casPH[t] = v;
    }
    if (t < NB*BS*HID) {
        g_w1h[t] = __float2half(w1[t] + w1[NB*BS*HID + t]);
        g_w2h[t] = __float2half(w2[t] + w2[NB*HID*BS + t]);
    }
    if (t < NB*HID) g_b1s[t] = b1[t];
    if (t < NB*BS)  g_b2s[t] = b2[t];
}

// ---------------------------------------------------------------------------
// casmul_f2h: pass 1. OUT_h[bt,m,n] = sum_k cas[m,k] IN_f[bt,k,n]
// Tile 128m x 64n x 128k. 8 warps; warp w owns rows [16w,16w+16) (cas A regs).
// fp32 input register-prefetched, packed to half smem [128][72h]; fp16 output.
// smem = 18432 B.
// ---------------------------------------------------------------------------
extern __shared__ uint32_t smu[];

__global__ __launch_bounds__(256, 2)
void casmul_f2h(const float* __restrict__ in, __half* __restrict__ out,
                int ncols, int total) {
    char* bS = (char*)smu;
    const int tid = threadIdx.x;
    const int w = tid >> 5, lane = tid & 31;
    const int g = lane >> 2, tig = lane & 3;
    const int l15 = lane & 15, lc8 = (lane >> 4) * 8;
    const int ntn = ncols >> 6;

    uint4 A[8];
    #pragma unroll
    for (int ks = 0; ks < 8; ks++)
        A[ks] = __ldg(&g_casPH[(w*8 + ks)*32 + lane]);

    float4 pf[8];
    int t = blockIdx.x;
    {
        int bt = t / ntn, nb = t - bt*ntn;
        const float* src = in + (size_t)bt * 128u * (size_t)ncols + nb*64;
        #pragma unroll
        for (int i = 0; i < 8; i++) {
            int idx = i*256 + tid;
            int k = idx >> 4, n4 = (idx & 15) << 2;
            pf[i] = *(const float4*)(src + (size_t)k * (size_t)ncols + n4);
        }
    }

    for (; t < total; t += gridDim.x) {
        __syncthreads();
        #pragma unroll
        for (int i = 0; i < 8; i++) {
            int idx = i*256 + tid;
            int k = idx >> 4, n4 = (idx & 15) << 2;
            uint2 u;
            u.x = pack2(pf[i].x, pf[i].y);
            u.y = pack2(pf[i].z, pf[i].w);
            *(uint2*)(bS + k*144 + n4*2) = u;
        }
        __syncthreads();

        int tn = t + gridDim.x;
        if (tn < total) {
            int bt = tn / ntn, nb = tn - bt*ntn;
            const float* src = in + (size_t)bt * 128u * (size_t)ncols + nb*64;
            #pragma unroll
            for (int i = 0; i < 8; i++) {
                int idx = i*256 + tid;
                int k = idx >> 4, n4 = (idx & 15) << 2;
                pf[i] = *(const float4*)(src + (size_t)k * (size_t)ncols + n4);
            }
        }

        float acc[8][4];
        #pragma unroll
        for (int i = 0; i < 8; i++)
            #pragma unroll
            for (int j = 0; j < 4; j++) acc[i][j] = 0.f;

        #pragma unroll
        for (int ks = 0; ks < 8; ks++) {
            #pragma unroll
            for (int nq = 0; nq < 4; nq++) {
                uint32_t b[4];
                ldsm4t(b, sptr(bS + (ks*16 + l15)*144 + (nq*16 + lc8)*2));
                mma16(acc[nq*2    ], A[ks].x, A[ks].y, A[ks].z, A[ks].w, b[0], b[1]);
                mma16(acc[nq*2 + 1], A[ks].x, A[ks].y, A[ks].z, A[ks].w, b[2], b[3]);
            }
        }

        {
            int bt = t / ntn, nb = t - bt*ntn;
            const size_t base = (size_t)bt * 128u * (size_t)ncols + nb*64;
            #pragma unroll
            for (int nf = 0; nf < 8; nf++) {
                int col = nf*8 + tig*2;
                #pragma unroll
                for (int r = 0; r < 2; r++) {
                    int row = w*16 + g + r*8;
                    *(uint32_t*)(out + base + (size_t)row * (size_t)ncols + col) =
                        pack2(acc[nf][r*2 + 0], acc[nf][r*2 + 1]);
                }
            }
        }
    }
}

// ---------------------------------------------------------------------------
// casmul_h2f: pass 5. OUT_f = scale * (cas @ IN_h) + add_f
// fp16 input cp.async double-buffered; fp32 output + residual.
// smem = 2 * 18432 = 36864 B.
// ---------------------------------------------------------------------------
__global__ __launch_bounds__(256, 2)
void casmul_h2f(const __half* __restrict__ in, float* __restrict__ out,
                const float* __restrict__ addsrc, float scale, int ncols, int total) {
    char* bS0 = (char*)smu;
    char* bS1 = bS0 + 18432;
    const int tid = threadIdx.x;
    const int w = tid >> 5, lane = tid & 31;
    const int g = lane >> 2, tig = lane & 3;
    const int l15 = lane & 15, lc8 = (lane >> 4) * 8;
    const int ntn = ncols >> 6;

    uint4 A[8];
    #pragma unroll
    for (int ks = 0; ks < 8; ks++)
        A[ks] = __ldg(&g_casPH[(w*8 + ks)*32 + lane]);

    // prefetch first tile into buf0
    int t = blockIdx.x;
    {
        int bt = t / ntn, nb = t - bt*ntn;
        const __half* src = in + (size_t)bt * 128u * (size_t)ncols + nb*64;
        #pragma unroll
        for (int i = 0; i < 4; i++) {
            int idx = i*256 + tid;
            int k = idx >> 3, seg = idx & 7;
            cp16(sptr(bS0 + k*144 + seg*16), src + (size_t)k * (size_t)ncols + seg*8);
        }
        CP_COMMIT();
    }

    int buf = 0;
    for (; t < total; t += gridDim.x) {
        int tn = t + gridDim.x;
        if (tn < total) {
            char* bN = buf ? bS0 : bS1;
            int bt = tn / ntn, nb = tn - bt*ntn;
            const __half* src = in + (size_t)bt * 128u * (size_t)ncols + nb*64;
            #pragma unroll
            for (int i = 0; i < 4; i++) {
                int idx = i*256 + tid;
                int k = idx >> 3, seg = idx & 7;
                cp16(sptr(bN + k*144 + seg*16), src + (size_t)k * (size_t)ncols + seg*8);
            }
            CP_COMMIT();
            CP_WAIT1();
        } else {
            CP_WAIT0();
        }
        __syncthreads();

        const char* bS = buf ? bS1 : bS0;
        float acc[8][4];
        #pragma unroll
        for (int i = 0; i < 8; i++)
            #pragma unroll
            for (int j = 0; j < 4; j++) acc[i][j] = 0.f;

        #pragma unroll
        for (int ks = 0; ks < 8; ks++) {
            #pragma unroll
            for (int nq = 0; nq < 4; nq++) {
                uint32_t b[4];
                ldsm4t(b, sptr(bS + (ks*16 + l15)*144 + (nq*16 + lc8)*2));
                mma16(acc[nq*2    ], A[ks].x, A[ks].y, A[ks].z, A[ks].w, b[0], b[1]);
                mma16(acc[nq*2 + 1], A[ks].x, A[ks].y, A[ks].z, A[ks].w, b[2], b[3]);
            }
        }

        {
            int bt = t / ntn, nb = t - bt*ntn;
            const size_t base = (size_t)bt * 128u * (size_t)ncols + nb*64;
            #pragma unroll
            for (int nf = 0; nf < 8; nf++) {
                int col = nf*8 + tig*2;
                #pragma unroll
                for (int r = 0; r < 2; r++) {
                    int row = w*16 + g + r*8;
                    size_t o = base + (size_t)row * (size_t)ncols + col;
                    float2 v;
                    v.x = acc[nf][r*2 + 0] * scale + addsrc[o];
                    v.y = acc[nf][r*2 + 1] * scale + addsrc[o + 1];
                    *(float2*)&out[o] = v;
                }
            }
        }
        __syncthreads();   // buffer reads done before it is re-prefetched
        buf ^= 1;
    }
}

// ---------------------------------------------------------------------------
// fused_h: per CTA (b, wcol, blk): tile [128h][128c], fp16 in/out.
//   T = cas @ X; MLP(4 chunks of 64 hidden); O2 = softthresh; Z = cas @ O2.
// 256 threads = 8 warps (4m x 2n). smem = 89088 B -> 2 CTAs/SM.
// ---------------------------------------------------------------------------
__global__ __launch_bounds__(256, 2)
void fused_h(const __half* __restrict__ in, __half* __restrict__ out) {
    char* buf = (char*)smu;                  // half [128][136] = 34816 B
    char* O1  = buf + 34816;                 // half [128][72]  = 18432 B
    char* Wb1 = O1 + 18432;                  // half [128][72]  = 18432 B
    char* Wb2 = Wb1 + 18432;                 // half [64][136]  = 17408 B

    const int tid  = threadIdx.x;
    const int bI   = blockIdx.x >> 7;
    const int wcol = blockIdx.x & 127;
    const int blk  = blockIdx.y;
    const size_t gbase = ((size_t)(bI*128)*128u + (size_t)wcol)*1024u + (size_t)blk*128u;

    // ---- load X tile [128h][128c] fp16 via cp.async ----
    #pragma unroll
    for (int i = 0; i < 8; i++) {
        int idx = i*256 + tid;
        int h = idx >> 4, seg = idx & 15;
        cp16(sptr(buf + h*272 + seg*16), in + gbase + (size_t)h*131072u + seg*8);
    }
    CP_COMMIT(); CP_WAIT0();

    const int wid = tid >> 5, lane = tid & 31;
    const int g = lane >> 2, tig = lane & 3;
    const int mw = wid & 3, nw = wid >> 2;   // 4m x 2n
    const int l15 = lane & 15, lc8 = (lane >> 4) * 8;
    const int m0 = mw*32;
    __syncthreads();

    // ================= Phase T: T = cas @ X =================
    {
        float acc[2][8][4];
        #pragma unroll
        for (int a = 0; a < 2; a++)
            #pragma unroll
            for (int b = 0; b < 8; b++)
                #pragma unroll
                for (int c = 0; c < 4; c++) acc[a][b][c] = 0.f;

        #pragma unroll
        for (int ks = 0; ks < 8; ks++) {
            uint4 A0 = __ldg(&g_casPH[((mw*2    )*8 + ks)*32 + lane]);
            uint4 A1 = __ldg(&g_casPH[((mw*2 + 1)*8 + ks)*32 + lane]);
            #pragma unroll
            for (int nq = 0; nq < 4; nq++) {
                uint32_t b[4];
                ldsm4t(b, sptr(buf + (ks*16 + l15)*272 + (nw*64 + nq*16 + lc8)*2));
                mma16(acc[0][nq*2    ], A0.x, A0.y, A0.z, A0.w, b[0], b[1]);
                mma16(acc[0][nq*2 + 1], A0.x, A0.y, A0.z, A0.w, b[2], b[3]);
                mma16(acc[1][nq*2    ], A1.x, A1.y, A1.z, A1.w, b[0], b[1]);
                mma16(acc[1][nq*2 + 1], A1.x, A1.y, A1.z, A1.w, b[2], b[3]);
            }
        }
        __syncthreads();   // all X reads done before overwrite
        #pragma unroll
        for (int mf = 0; mf < 2; mf++)
            #pragma unroll
            for (int nf = 0; nf < 8; nf++) {
                int n = nw*64 + nf*8 + tig*2;
                #pragma unroll
                for (int r = 0; r < 2; r++) {
                    int m = m0 + mf*16 + g + r*8;
                    *(uint32_t*)(buf + m*272 + n*2) =
                        pack2(acc[mf][nf][r*2 + 0], acc[mf][nf][r*2 + 1]);
                }
            }
        __syncthreads();   // T complete
    }

    // ================= MLP: 4 chunks of 64 hidden =================
    const __half* W1 = g_w1h + blk*BS*HID;
    const __half* W2 = g_w2h + blk*HID*BS;

    float acc2[2][8][4];
    #pragma unroll
    for (int a = 0; a < 2; a++)
        #pragma unroll
        for (int b = 0; b < 8; b++)
            #pragma unroll
            for (int c = 0; c < 4; c++) acc2[a][b][c] = 0.f;

    for (int ch = 0; ch < 4; ch++) {
        // stage W1 chunk [128k][64n] pitch 72 + W2 chunk [64k][128n] pitch 136
        #pragma unroll
        for (int i = 0; i < 4; i++) {
            int idx = i*256 + tid;
            int k = idx >> 3, seg = idx & 7;
            cp16(sptr(Wb1 + k*144 + seg*16), W1 + k*HID + ch*64 + seg*8);
        }
        #pragma unroll
        for (int i = 0; i < 4; i++) {
            int idx = i*256 + tid;
            int k = idx >> 4, seg = idx & 15;
            cp16(sptr(Wb2 + k*272 + seg*16), W2 + (size_t)(ch*64 + k)*BS + seg*8);
        }
        CP_COMMIT(); CP_WAIT0(); __syncthreads();

        // ---- GEMM1: [128,128]@[128,64], warp n-range 32 ----
        float acc1[2][4][4];
        #pragma unroll
        for (int a = 0; a < 2; a++)
            #pragma unroll
            for (int b = 0; b < 4; b++)
                #pragma unroll
                for (int c = 0; c < 4; c++) acc1[a][b][c] = 0.f;

        #pragma unroll
        for (int ks = 0; ks < 8; ks++) {
            uint32_t a0[4], a1[4];
            ldsm4(a0, sptr(buf + (m0      + l15)*272 + (ks*16 + lc8)*2));
            ldsm4(a1, sptr(buf + (m0 + 16 + l15)*272 + (ks*16 + lc8)*2));
            #pragma unroll
            for (int nq = 0; nq < 2; nq++) {
                uint32_t b[4];
                ldsm4t(b, sptr(Wb1 + (ks*16 + l15)*144 + (nw*32 + nq*16 + lc8)*2));
                mma16(acc1[0][nq*2    ], a0[0], a0[1], a0[2], a0[3], b[0], b[1]);
                mma16(acc1[0][nq*2 + 1], a0[0], a0[1], a0[2], a0[3], b[2], b[3]);
                mma16(acc1[1][nq*2    ], a1[0], a1[1], a1[2], a1[3], b[0], b[1]);
                mma16(acc1[1][nq*2 + 1], a1[0], a1[1], a1[2], a1[3], b[2], b[3]);
            }
        }

        // ---- bias + relu -> O1 [128][64] pitch 72 ----
        #pragma unroll
        for (int mf = 0; mf < 2; mf++)
            #pragma unroll
            for (int nf = 0; nf < 4; nf++) {
                int nc = nw*32 + nf*8 + tig*2;
                float bx = g_b1s[blk*HID + ch*64 + nc];
                float by = g_b1s[blk*HID + ch*64 + nc + 1];
                #pragma unroll
                for (int r = 0; r < 2; r++) {
                    int m = m0 + mf*16 + g + r*8;
                    *(uint32_t*)(O1 + m*144 + nc*2) =
                        pack2(fmaxf(acc1[mf][nf][r*2 + 0] + bx, 0.f),
                              fmaxf(acc1[mf][nf][r*2 + 1] + by, 0.f));
                }
            }
        __syncthreads();   // O1 complete

        // ---- GEMM2 partial: [128,64]@[64,128], warp n-range 64 ----
        #pragma unroll
        for (int ks = 0; ks < 4; ks++) {
            uint32_t a0[4], a1[4];
            ldsm4(a0, sptr(O1 + (m0      + l15)*144 + (ks*16 + lc8)*2));
            ldsm4(a1, sptr(O1 + (m0 + 16 + l15)*144 + (ks*16 + lc8)*2));
            #pragma unroll
            for (int nq = 0; nq < 4; nq++) {
                uint32_t b[4];
                ldsm4t(b, sptr(Wb2 + (ks*16 + l15)*272 + (nw*64 + nq*16 + lc8)*2));
                mma16(acc2[0][nq*2    ], a0[0], a0[1], a0[2], a0[3], b[0], b[1]);
                mma16(acc2[0][nq*2 + 1], a0[0], a0[1], a0[2], a0[3], b[2], b[3]);
                mma16(acc2[1][nq*2    ], a1[0], a1[1], a1[2], a1[3], b[0], b[1]);
                mma16(acc2[1][nq*2 + 1], a1[0], a1[1], a1[2], a1[3], b[2], b[3]);
            }
        }
        __syncthreads();   // Wb/O1 reads done before next chunk restage
    }

    // ---- O2 = softthresh(acc2 + b2) -> buf ----
    #pragma unroll
    for (int mf = 0; mf < 2; mf++)
        #pragma unroll
        for (int nf = 0; nf < 8; nf++) {
            int n = nw*64 + nf*8 + tig*2;
            float bx = g_b2s[blk*BS + n];
            float by = g_b2s[blk*BS + n + 1];
            #pragma unroll
            for (int r = 0; r < 2; r++) {
                int m = m0 + mf*16 + g + r*8;
                *(uint32_t*)(buf + m*272 + n*2) =
                    pack2(sthr(acc2[mf][nf][r*2 + 0] + bx),
                          sthr(acc2[mf][nf][r*2 + 1] + by));
            }
        }
    __syncthreads();

    // ================= Phase Z: Z = cas @ O2 -> gmem (fp16) =================
    {
        float acc[2][8][4];
        #pragma unroll
        for (int a = 0; a < 2; a++)
            #pragma unroll
            for (int b = 0; b < 8; b++)
                #pragma unroll
                for (int c = 0; c < 4; c++) acc[a][b][c] = 0.f;

        #pragma unroll
        for (int ks = 0; ks < 8; ks++) {
            uint4 A0 = __ldg(&g_casPH[((mw*2    )*8 + ks)*32 + lane]);
            uint4 A1 = __ldg(&g_casPH[((mw*2 + 1)*8 + ks)*32 + lane]);
            #pragma unroll
            for (int nq = 0; nq < 4; nq++) {
                uint32_t b[4];
                ldsm4t(b, sptr(buf + (ks*16 + l15)*272 + (nw*64 + nq*16 + lc8)*2));
                mma16(acc[0][nq*2    ], A0.x, A0.y, A0.z, A0.w, b[0], b[1]);
                mma16(acc[0][nq*2 + 1], A0.x, A0.y, A0.z, A0.w, b[2], b[3]);
                mma16(acc[1][nq*2    ], A1.x, A1.y, A1.z, A1.w, b[0], b[1]);
                mma16(acc[1][nq*2 + 1], A1.x, A1.y, A1.z, A1.w, b[2], b[3]);
            }
        }

        #pragma unroll
        for (int mf = 0; mf < 2; mf++)
            #pragma unroll
            for (int nf = 0; nf < 8; nf++) {
                int n = nw*64 + nf*8 + tig*2;
                #pragma unroll
                for (int r = 0; r < 2; r++) {
                    int m = m0 + mf*16 + g + r*8;
                    *(uint32_t*)(out + gbase + (size_t)m*131072u + n) =
                        pack2(acc[mf][nf][r*2 + 0], acc[mf][nf][r*2 + 1]);
                }
            }
    }
}

// ---------------------------------------------------------------------------
extern "C" void kernel_launch(void* const* d_in, const int* in_sizes, int n_in,
                              void* d_out, int out_size) {
    const float* x  = (const float*)d_in[0];
    const float* w1 = (const float*)d_in[1];
    const float* b1 = (const float*)d_in[2];
    const float* w2 = (const float*)d_in[3];
    const float* b2 = (const float*)d_in[4];
    float* out = (float*)d_out;

    void *p1, *p2;
    cudaGetSymbolAddress(&p1, g_bh1);
    cudaGetSymbolAddress(&p2, g_bh2);
    __half* bh1 = (__half*)p1;
    __half* bh2 = (__half*)p2;

    const int CAS1_SMEM = 18432;
    const int CAS2_SMEM = 36864;
    const int MID_SMEM  = 34816 + 18432 + 18432 + 17408;   // 89088
    cudaFuncSetAttribute(casmul_f2h, cudaFuncAttributeMaxDynamicSharedMemorySize, CAS1_SMEM);
    cudaFuncSetAttribute(casmul_h2f, cudaFuncAttributeMaxDynamicSharedMemorySize, CAS2_SMEM);
    cudaFuncSetAttribute(fused_h,    cudaFuncAttributeMaxDynamicSharedMemorySize, MID_SMEM);

    prep_kernel<<<1024, 256>>>(w1, b1, w2, b2);

    const int GRID = 296;
    const int T1 = (CC/64) * (BB*HH);      // 8192 tiles (W-direction)

    // pass 1: forward transform along W (fp32 -> fp16)
    casmul_f2h<<<GRID, 256, CAS1_SMEM>>>(x, bh1, CC, T1);

    // fused: H-transform + block MLP + soft-threshold + inverse H-transform
    fused_h<<<dim3(BB*WW, NB), 256, MID_SMEM>>>(bh1, bh2);

    // pass 5: inverse transform along W, scale 1/(H*W), residual add (fp16 -> fp32)
    casmul_h2f<<<GRID, 256, CAS2_SMEM>>>(bh2, out, x, 1.0f/(HH*WW), CC, T1);
}

// round 9
// speedup vs baseline: 2.1254x; 1.0031x over previous
#include <cuda_runtime.h>
#include <cuda_fp16.h>
#include <stdint.h>

#define BB 4
#define HH 128
#define WW 128
#define CC 1024
#define NB 8
#define BS 128
#define HID 256
#define LAM 0.01f
#define NTOT (BB*HH*WW*CC)

// ---------------- scratch (device .bss, no allocation) ----------------
// fp16 intermediates overlay the big buffers
__device__ __align__(128) __half g_bh1[NTOT];
__device__ __align__(128) __half g_bh2[NTOT];
// cas matrix packed as m16n8k16 A-fragments (half2 in each u32):
// index (mt*8 + ks)*32 + lane -> uint4 {a0,a1,a2,a3}
__device__ __align__(16) uint4 g_casPH[8*8*32];
__device__ __align__(16) __half g_w1h[NB*BS*HID];   // folded [blk][i=128][o=256]
__device__ __align__(16) __half g_w2h[NB*HID*BS];   // folded [blk][o=256][i=128]
__device__ float g_b1s[NB*HID];
__device__ float g_b2s[NB*BS];

// ---------------- helpers ----------------
__device__ __forceinline__ void mma16(float* c, uint32_t a0, uint32_t a1, uint32_t a2, uint32_t a3,
                                      uint32_t b0, uint32_t b1) {
    asm volatile("mma.sync.aligned.m16n8k16.row.col.f32.f16.f16.f32 "
                 "{%0,%1,%2,%3}, {%4,%5,%6,%7}, {%8,%9}, {%0,%1,%2,%3};"
                 : "+f"(c[0]), "+f"(c[1]), "+f"(c[2]), "+f"(c[3])
                 : "r"(a0), "r"(a1), "r"(a2), "r"(a3), "r"(b0), "r"(b1));
}
__device__ __forceinline__ void ldsm4(uint32_t* r, uint32_t a) {
    asm volatile("ldmatrix.sync.aligned.m8n8.x4.shared.b16 {%0,%1,%2,%3}, [%4];"
                 : "=r"(r[0]), "=r"(r[1]), "=r"(r[2]), "=r"(r[3]) : "r"(a));
}
__device__ __forceinline__ void ldsm4t(uint32_t* r, uint32_t a) {
    asm volatile("ldmatrix.sync.aligned.m8n8.x4.trans.shared.b16 {%0,%1,%2,%3}, [%4];"
                 : "=r"(r[0]), "=r"(r[1]), "=r"(r[2]), "=r"(r[3]) : "r"(a));
}
__device__ __forceinline__ void cp16(uint32_t saddr, const void* gptr) {
    asm volatile("cp.async.cg.shared.global [%0], [%1], 16;" :: "r"(saddr), "l"(gptr));
}
#define CP_COMMIT() asm volatile("cp.async.commit_group;")
#define CP_WAIT1()  asm volatile("cp.async.wait_group 1;")
#define CP_WAIT0()  asm volatile("cp.async.wait_group 0;")
__device__ __forceinline__ uint32_t sptr(const void* p) {
    return (uint32_t)__cvta_generic_to_shared(p);
}
__device__ __forceinline__ uint32_t pack2(float a, float b) {
    __half2 h = __floats2half2_rn(a, b);
    return *reinterpret_cast<uint32_t*>(&h);
}
__device__ __forceinline__ float sthr(float z) {
    return (z > LAM) ? (z - LAM) : ((z < -LAM) ? (z + LAM) : 0.f);
}

// ---------------- prep ----------------
__device__ __forceinline__ float casv(int m, int k) {
    float s, c;
    sincospif((float)((m * k) & 127) * (1.0f/64.0f), &s, &c);
    return c + s;
}

__global__ void prep_kernel(const float* __restrict__ w1, const float* __restrict__ b1,
                            const float* __restrict__ w2, const float* __restrict__ b2) {
    int t = blockIdx.x * blockDim.x + threadIdx.x;
    if (t < 8*8*32) {
        int lane = t & 31, ks = (t >> 5) & 7, mt = t >> 8;
        int g = lane >> 2, tig = lane & 3;
        int m0 = mt*16 + g, k0 = ks*16 + 2*tig;
        uint4 v;
        v.x = pack2(casv(m0,     k0),     casv(m0,     k0 + 1));
        v.y = pack2(casv(m0 + 8, k0),     casv(m0 + 8, k0 + 1));
        v.z = pack2(casv(m0,     k0 + 8), casv(m0,     k0 + 9));
        v.w = pack2(casv(m0 + 8, k0 + 8), casv(m0 + 8, k0 + 9));
        g_casPH[t] = v;
    }
    if (t < NB*BS*HID) {
        g_w1h[t] = __float2half(w1[t] + w1[NB*BS*HID + t]);
        g_w2h[t] = __float2half(w2[t] + w2[NB*HID*BS + t]);
    }
    if (t < NB*HID) g_b1s[t] = b1[t];
    if (t < NB*BS)  g_b2s[t] = b2[t];
}

// ---------------------------------------------------------------------------
// casmul_f2h: pass 1. OUT_h[bt,m,n] = sum_k cas[m,k] IN_f[bt,k,n]
// Tile 128m x 64n x 128k. 8 warps; warp w owns rows [16w,16w+16) (cas A regs).
// fp32 input register-prefetched, packed to half smem [128][72h]; fp16 output.
// smem = 18432 B.
// ---------------------------------------------------------------------------
extern __shared__ uint32_t smu[];

__global__ __launch_bounds__(256, 2)
void casmul_f2h(const float* __restrict__ in, __half* __restrict__ out,
                int ncols, int total) {
    char* bS = (char*)smu;
    const int tid = threadIdx.x;
    const int w = tid >> 5, lane = tid & 31;
    const int g = lane >> 2, tig = lane & 3;
    const int l15 = lane & 15, lc8 = (lane >> 4) * 8;
    const int ntn = ncols >> 6;

    uint4 A[8];
    #pragma unroll
    for (int ks = 0; ks < 8; ks++)
        A[ks] = __ldg(&g_casPH[(w*8 + ks)*32 + lane]);

    float4 pf[8];
    int t = blockIdx.x;
    {
        int bt = t / ntn, nb = t - bt*ntn;
        const float* src = in + (size_t)bt * 128u * (size_t)ncols + nb*64;
        #pragma unroll
        for (int i = 0; i < 8; i++) {
            int idx = i*256 + tid;
            int k = idx >> 4, n4 = (idx & 15) << 2;
            pf[i] = *(const float4*)(src + (size_t)k * (size_t)ncols + n4);
        }
    }

    for (; t < total; t += gridDim.x) {
        __syncthreads();
        #pragma unroll
        for (int i = 0; i < 8; i++) {
            int idx = i*256 + tid;
            int k = idx >> 4, n4 = (idx & 15) << 2;
            uint2 u;
            u.x = pack2(pf[i].x, pf[i].y);
            u.y = pack2(pf[i].z, pf[i].w);
            *(uint2*)(bS + k*144 + n4*2) = u;
        }
        __syncthreads();

        int tn = t + gridDim.x;
        if (tn < total) {
            int bt = tn / ntn, nb = tn - bt*ntn;
            const float* src = in + (size_t)bt * 128u * (size_t)ncols + nb*64;
            #pragma unroll
            for (int i = 0; i < 8; i++) {
                int idx = i*256 + tid;
                int k = idx >> 4, n4 = (idx & 15) << 2;
                pf[i] = *(const float4*)(src + (size_t)k * (size_t)ncols + n4);
            }
        }

        float acc[8][4];
        #pragma unroll
        for (int i = 0; i < 8; i++)
            #pragma unroll
            for (int j = 0; j < 4; j++) acc[i][j] = 0.f;

        #pragma unroll
        for (int ks = 0; ks < 8; ks++) {
            #pragma unroll
            for (int nq = 0; nq < 4; nq++) {
                uint32_t b[4];
                ldsm4t(b, sptr(bS + (ks*16 + l15)*144 + (nq*16 + lc8)*2));
                mma16(acc[nq*2    ], A[ks].x, A[ks].y, A[ks].z, A[ks].w, b[0], b[1]);
                mma16(acc[nq*2 + 1], A[ks].x, A[ks].y, A[ks].z, A[ks].w, b[2], b[3]);
            }
        }

        {
            int bt = t / ntn, nb = t - bt*ntn;
            const size_t base = (size_t)bt * 128u * (size_t)ncols + nb*64;
            #pragma unroll
            for (int nf = 0; nf < 8; nf++) {
                int col = nf*8 + tig*2;
                #pragma unroll
                for (int r = 0; r < 2; r++) {
                    int row = w*16 + g + r*8;
                    *(uint32_t*)(out + base + (size_t)row * (size_t)ncols + col) =
                        pack2(acc[nf][r*2 + 0], acc[nf][r*2 + 1]);
                }
            }
        }
    }
}

// ---------------------------------------------------------------------------
// casmul_h2f: pass 5. OUT_f = scale * (cas @ IN_h) + add_f
// fp16 input cp.async double-buffered; fp32 output + residual.
// smem = 2 * 18432 = 36864 B.
// ---------------------------------------------------------------------------
__global__ __launch_bounds__(256, 2)
void casmul_h2f(const __half* __restrict__ in, float* __restrict__ out,
                const float* __restrict__ addsrc, float scale, int ncols, int total) {
    char* bS0 = (char*)smu;
    char* bS1 = bS0 + 18432;
    const int tid = threadIdx.x;
    const int w = tid >> 5, lane = tid & 31;
    const int g = lane >> 2, tig = lane & 3;
    const int l15 = lane & 15, lc8 = (lane >> 4) * 8;
    const int ntn = ncols >> 6;

    uint4 A[8];
    #pragma unroll
    for (int ks = 0; ks < 8; ks++)
        A[ks] = __ldg(&g_casPH[(w*8 + ks)*32 + lane]);

    // prefetch first tile into buf0
    int t = blockIdx.x;
    {
        int bt = t / ntn, nb = t - bt*ntn;
        const __half* src = in + (size_t)bt * 128u * (size_t)ncols + nb*64;
        #pragma unroll
        for (int i = 0; i < 4; i++) {
            int idx = i*256 + tid;
            int k = idx >> 3, seg = idx & 7;
            cp16(sptr(bS0 + k*144 + seg*16), src + (size_t)k * (size_t)ncols + seg*8);
        }
        CP_COMMIT();
    }

    int buf = 0;
    for (; t < total; t += gridDim.x) {
        int tn = t + gridDim.x;
        if (tn < total) {
            char* bN = buf ? bS0 : bS1;
            int bt = tn / ntn, nb = tn - bt*ntn;
            const __half* src = in + (size_t)bt * 128u * (size_t)ncols + nb*64;
            #pragma unroll
            for (int i = 0; i < 4; i++) {
                int idx = i*256 + tid;
                int k = idx >> 3, seg = idx & 7;
                cp16(sptr(bN + k*144 + seg*16), src + (size_t)k * (size_t)ncols + seg*8);
            }
            CP_COMMIT();
            CP_WAIT1();
        } else {
            CP_WAIT0();
        }
        __syncthreads();

        const char* bS = buf ? bS1 : bS0;
        float acc[8][4];
        #pragma unroll
        for (int i = 0; i < 8; i++)
            #pragma unroll
            for (int j = 0; j < 4; j++) acc[i][j] = 0.f;

        #pragma unroll
        for (int ks = 0; ks < 8; ks++) {
            #pragma unroll
            for (int nq = 0; nq < 4; nq++) {
                uint32_t b[4];
                ldsm4t(b, sptr(bS + (ks*16 + l15)*144 + (nq*16 + lc8)*2));
                mma16(acc[nq*2    ], A[ks].x, A[ks].y, A[ks].z, A[ks].w, b[0], b[1]);
                mma16(acc[nq*2 + 1], A[ks].x, A[ks].y, A[ks].z, A[ks].w, b[2], b[3]);
            }
        }

        {
            int bt = t / ntn, nb = t - bt*ntn;
            const size_t base = (size_t)bt * 128u * (size_t)ncols + nb*64;
            #pragma unroll
            for (int nf = 0; nf < 8; nf++) {
                int col = nf*8 + tig*2;
                #pragma unroll
                for (int r = 0; r < 2; r++) {
                    int row = w*16 + g + r*8;
                    size_t o = base + (size_t)row * (size_t)ncols + col;
                    float2 v;
                    v.x = acc[nf][r*2 + 0] * scale + addsrc[o];
                    v.y = acc[nf][r*2 + 1] * scale + addsrc[o + 1];
                    *(float2*)&out[o] = v;
                }
            }
        }
        __syncthreads();   // buffer reads done before it is re-prefetched
        buf ^= 1;
    }
}

// ---------------------------------------------------------------------------
// fused_h: per CTA (b, wcol, blk): tile [128h][128c], fp16 in/out.
//   T = cas @ X; MLP(4 chunks of 64 hidden); O2 = softthresh; Z = cas @ O2.
// 256 threads = 8 warps (4m x 2n). smem = 89088 B -> 2 CTAs/SM.
// ---------------------------------------------------------------------------
__global__ __launch_bounds__(256, 2)
void fused_h(const __half* __restrict__ in, __half* __restrict__ out) {
    char* buf = (char*)smu;                  // half [128][136] = 34816 B
    char* O1  = buf + 34816;                 // half [128][72]  = 18432 B
    char* Wb1 = O1 + 18432;                  // half [128][72]  = 18432 B
    char* Wb2 = Wb1 + 18432;                 // half [64][136]  = 17408 B

    const int tid  = threadIdx.x;
    const int bI   = blockIdx.x >> 7;
    const int wcol = blockIdx.x & 127;
    const int blk  = blockIdx.y;
    const size_t gbase = ((size_t)(bI*128)*128u + (size_t)wcol)*1024u + (size_t)blk*128u;

    // ---- load X tile [128h][128c] fp16 via cp.async ----
    #pragma unroll
    for (int i = 0; i < 8; i++) {
        int idx = i*256 + tid;
        int h = idx >> 4, seg = idx & 15;
        cp16(sptr(buf + h*272 + seg*16), in + gbase + (size_t)h*131072u + seg*8);
    }
    CP_COMMIT(); CP_WAIT0();

    const int wid = tid >> 5, lane = tid & 31;
    const int g = lane >> 2, tig = lane & 3;
    const int mw = wid & 3, nw = wid >> 2;   // 4m x 2n
    const int l15 = lane & 15, lc8 = (lane >> 4) * 8;
    const int m0 = mw*32;
    __syncthreads();

    // ================= Phase T: T = cas @ X =================
    {
        float acc[2][8][4];
        #pragma unroll
        for (int a = 0; a < 2; a++)
            #pragma unroll
            for (int b = 0; b < 8; b++)
                #pragma unroll
                for (int c = 0; c < 4; c++) acc[a][b][c] = 0.f;

        #pragma unroll
        for (int ks = 0; ks < 8; ks++) {
            uint4 A0 = __ldg(&g_casPH[((mw*2    )*8 + ks)*32 + lane]);
            uint4 A1 = __ldg(&g_casPH[((mw*2 + 1)*8 + ks)*32 + lane]);
            #pragma unroll
            for (int nq = 0; nq < 4; nq++) {
                uint32_t b[4];
                ldsm4t(b, sptr(buf + (ks*16 + l15)*272 + (nw*64 + nq*16 + lc8)*2));
                mma16(acc[0][nq*2    ], A0.x, A0.y, A0.z, A0.w, b[0], b[1]);
                mma16(acc[0][nq*2 + 1], A0.x, A0.y, A0.z, A0.w, b[2], b[3]);
                mma16(acc[1][nq*2    ], A1.x, A1.y, A1.z, A1.w, b[0], b[1]);
                mma16(acc[1][nq*2 + 1], A1.x, A1.y, A1.z, A1.w, b[2], b[3]);
            }
        }
        __syncthreads();   // all X reads done before overwrite
        #pragma unroll
        for (int mf = 0; mf < 2; mf++)
            #pragma unroll
            for (int nf = 0; nf < 8; nf++) {
                int n = nw*64 + nf*8 + tig*2;
                #pragma unroll
                for (int r = 0; r < 2; r++) {
                    int m = m0 + mf*16 + g + r*8;
                    *(uint32_t*)(buf + m*272 + n*2) =
                        pack2(acc[mf][nf][r*2 + 0], acc[mf][nf][r*2 + 1]);
                }
            }
        __syncthreads();   // T complete
    }

    // ================= MLP: 4 chunks of 64 hidden =================
    const __half* W1 = g_w1h + blk*BS*HID;
    const __half* W2 = g_w2h + blk*HID*BS;

    float acc2[2][8][4];
    #pragma unroll
    for (int a = 0; a < 2; a++)
        #pragma unroll
        for (int b = 0; b < 8; b++)
            #pragma unroll
            for (int c = 0; c < 4; c++) acc2[a][b][c] = 0.f;

    for (int ch = 0; ch < 4; ch++) {
        // stage W1 chunk [128k][64n] pitch 72 + W2 chunk [64k][128n] pitch 136
        #pragma unroll
        for (int i = 0; i < 4; i++) {
            int idx = i*256 + tid;
            int k = idx >> 3, seg = idx & 7;
            cp16(sptr(Wb1 + k*144 + seg*16), W1 + k*HID + ch*64 + seg*8);
        }
        #pragma unroll
        for (int i = 0; i < 4; i++) {
            int idx = i*256 + tid;
            int k = idx >> 4, seg = idx & 15;
            cp16(sptr(Wb2 + k*272 + seg*16), W2 + (size_t)(ch*64 + k)*BS + seg*8);
        }
        CP_COMMIT(); CP_WAIT0(); __syncthreads();

        // ---- GEMM1: [128,128]@[128,64], warp n-range 32 ----
        float acc1[2][4][4];
        #pragma unroll
        for (int a = 0; a < 2; a++)
            #pragma unroll
            for (int b = 0; b < 4; b++)
                #pragma unroll
                for (int c = 0; c < 4; c++) acc1[a][b][c] = 0.f;

        #pragma unroll
        for (int ks = 0; ks < 8; ks++) {
            uint32_t a0[4], a1[4];
            ldsm4(a0, sptr(buf + (m0      + l15)*272 + (ks*16 + lc8)*2));
            ldsm4(a1, sptr(buf + (m0 + 16 + l15)*272 + (ks*16 + lc8)*2));
            #pragma unroll
            for (int nq = 0; nq < 2; nq++) {
                uint32_t b[4];
                ldsm4t(b, sptr(Wb1 + (ks*16 + l15)*144 + (nw*32 + nq*16 + lc8)*2));
                mma16(acc1[0][nq*2    ], a0[0], a0[1], a0[2], a0[3], b[0], b[1]);
                mma16(acc1[0][nq*2 + 1], a0[0], a0[1], a0[2], a0[3], b[2], b[3]);
                mma16(acc1[1][nq*2    ], a1[0], a1[1], a1[2], a1[3], b[0], b[1]);
                mma16(acc1[1][nq*2 + 1], a1[0], a1[1], a1[2], a1[3], b[2], b[3]);
            }
        }

        // ---- bias + relu -> O1 [128][64] pitch 72 ----
        #pragma unroll
        for (int mf = 0; mf < 2; mf++)
            #pragma unroll
            for (int nf = 0; nf < 4; nf++) {
                int nc = nw*32 + nf*8 + tig*2;
                float bx = g_b1s[blk*HID + ch*64 + nc];
                float by = g_b1s[blk*HID + ch*64 + nc + 1];
                #pragma unroll
                for (int r = 0; r < 2; r++) {
                    int m = m0 + mf*16 + g + r*8;
                    *(uint32_t*)(O1 + m*144 + nc*2) =
                        pack2(fmaxf(acc1[mf][nf][r*2 + 0] + bx, 0.f),
                              fmaxf(acc1[mf][nf][r*2 + 1] + by, 0.f));
                }
            }
        __syncthreads();   // O1 complete

        // ---- GEMM2 partial: [128,64]@[64,128], warp n-range 64 ----
        #pragma unroll
        for (int ks = 0; ks < 4; ks++) {
            uint32_t a0[4], a1[4];
            ldsm4(a0, sptr(O1 + (m0      + l15)*144 + (ks*16 + lc8)*2));
            ldsm4(a1, sptr(O1 + (m0 + 16 + l15)*144 + (ks*16 + lc8)*2));
            #pragma unroll
            for (int nq = 0; nq < 4; nq++) {
                uint32_t b[4];
                ldsm4t(b, sptr(Wb2 + (ks*16 + l15)*272 + (nw*64 + nq*16 + lc8)*2));
                mma16(acc2[0][nq*2    ], a0[0], a0[1], a0[2], a0[3], b[0], b[1]);
                mma16(acc2[0][nq*2 + 1], a0[0], a0[1], a0[2], a0[3], b[2], b[3]);
                mma16(acc2[1][nq*2    ], a1[0], a1[1], a1[2], a1[3], b[0], b[1]);
                mma16(acc2[1][nq*2 + 1], a1[0], a1[1], a1[2], a1[3], b[2], b[3]);
            }
        }
        __syncthreads();   // Wb/O1 reads done before next chunk restage
    }

    // ---- O2 = softthresh(acc2 + b2) -> buf ----
    #pragma unroll
    for (int mf = 0; mf < 2; mf++)
        #pragma unroll
        for (int nf = 0; nf < 8; nf++) {
            int n = nw*64 + nf*8 + tig*2;
            float bx = g_b2s[blk*BS + n];
            float by = g_b2s[blk*BS + n + 1];
            #pragma unroll
            for (int r = 0; r < 2; r++) {
                int m = m0 + mf*16 + g + r*8;
                *(uint32_t*)(buf + m*272 + n*2) =
                    pack2(sthr(acc2[mf][nf][r*2 + 0] + bx),
                          sthr(acc2[mf][nf][r*2 + 1] + by));
            }
        }
    __syncthreads();

    // ================= Phase Z: Z = cas @ O2 -> gmem (fp16) =================
    {
        float acc[2][8][4];
        #pragma unroll
        for (int a = 0; a < 2; a++)
            #pragma unroll
            for (int b = 0; b < 8; b++)
                #pragma unroll
                for (int c = 0; c < 4; c++) acc[a][b][c] = 0.f;

        #pragma unroll
        for (int ks = 0; ks < 8; ks++) {
            uint4 A0 = __ldg(&g_casPH[((mw*2    )*8 + ks)*32 + lane]);
            uint4 A1 = __ldg(&g_casPH[((mw*2 + 1)*8 + ks)*32 + lane]);
            #pragma unroll
            for (int nq = 0; nq < 4; nq++) {
                uint32_t b[4];
                ldsm4t(b, sptr(buf + (ks*16 + l15)*272 + (nw*64 + nq*16 + lc8)*2));
                mma16(acc[0][nq*2    ], A0.x, A0.y, A0.z, A0.w, b[0], b[1]);
                mma16(acc[0][nq*2 + 1], A0.x, A0.y, A0.z, A0.w, b[2], b[3]);
                mma16(acc[1][nq*2    ], A1.x, A1.y, A1.z, A1.w, b[0], b[1]);
                mma16(acc[1][nq*2 + 1], A1.x, A1.y, A1.z, A1.w, b[2], b[3]);
            }
        }

        #pragma unroll
        for (int mf = 0; mf < 2; mf++)
            #pragma unroll
            for (int nf = 0; nf < 8; nf++) {
                int n = nw*64 + nf*8 + tig*2;
                #pragma unroll
                for (int r = 0; r < 2; r++) {
                    int m = m0 + mf*16 + g + r*8;
                    *(uint32_t*)(out + gbase + (size_t)m*131072u + n) =
                        pack2(acc[mf][nf][r*2 + 0], acc[mf][nf][r*2 + 1]);
                }
            }
    }
}

// ---------------------------------------------------------------------------
extern "C" void kernel_launch(void* const* d_in, const int* in_sizes, int n_in,
                              void* d_out, int out_size) {
    const float* x  = (const float*)d_in[0];
    const float* w1 = (const float*)d_in[1];
    const float* b1 = (const float*)d_in[2];
    const float* w2 = (const float*)d_in[3];
    const float* b2 = (const float*)d_in[4];
    float* out = (float*)d_out;

    void *p1, *p2;
    cudaGetSymbolAddress(&p1, g_bh1);
    cudaGetSymbolAddress(&p2, g_bh2);
    __half* bh1 = (__half*)p1;
    __half* bh2 = (__half*)p2;

    const int CAS1_SMEM = 18432;
    const int CAS2_SMEM = 36864;
    const int MID_SMEM  = 34816 + 18432 + 18432 + 17408;   // 89088
    cudaFuncSetAttribute(casmul_f2h, cudaFuncAttributeMaxDynamicSharedMemorySize, CAS1_SMEM);
    cudaFuncSetAttribute(casmul_h2f, cudaFuncAttributeMaxDynamicSharedMemorySize, CAS2_SMEM);
    cudaFuncSetAttribute(fused_h,    cudaFuncAttributeMaxDynamicSharedMemorySize, MID_SMEM);

    prep_kernel<<<1024, 256>>>(w1, b1, w2, b2);

    const int GRID = 296;
    const int T1 = (CC/64) * (BB*HH);      // 8192 tiles (W-direction)

    // pass 1: forward transform along W (fp32 -> fp16)
    casmul_f2h<<<GRID, 256, CAS1_SMEM>>>(x, bh1, CC, T1);

    // fused: H-transform + block MLP + soft-threshold + inverse H-transform
    fused_h<<<dim3(BB*WW, NB), 256, MID_SMEM>>>(bh1, bh2);

    // pass 5: inverse transform along W, scale 1/(H*W), residual add (fp16 -> fp32)
    casmul_h2f<<<GRID, 256, CAS2_SMEM>>>(bh2, out, x, 1.0f/(HH*WW), CC, T1);
}

// round 11
// speedup vs baseline: 2.1872x; 1.0291x over previous
#include <cuda_runtime.h>
#include <cuda_fp16.h>
#include <stdint.h>

#define BB 4
#define HH 128
#define WW 128
#define CC 1024
#define NB 8
#define BS 128
#define HID 256
#define LAM 0.01f
#define NTOT (BB*HH*WW*CC)

__device__ __align__(128) __half g_bh1[NTOT];
__device__ __align__(128) __half g_bh2[NTOT];
__device__ __align__(16) uint4 g_casPH[8*8*32];   // m16n8k16 A-fragment layout
__device__ __align__(16) __half g_w1h[NB*BS*HID];
__device__ __align__(16) __half g_w2h[NB*HID*BS];
__device__ float g_b1s[NB*HID];
__device__ float g_b2s[NB*BS];

// ---------------- helpers ----------------
__device__ __forceinline__ void mma16(float* c, uint32_t a0, uint32_t a1, uint32_t a2, uint32_t a3,
                                      uint32_t b0, uint32_t b1) {
    asm volatile("mma.sync.aligned.m16n8k16.row.col.f32.f16.f16.f32 "
                 "{%0,%1,%2,%3}, {%4,%5,%6,%7}, {%8,%9}, {%0,%1,%2,%3};"
                 : "+f"(c[0]), "+f"(c[1]), "+f"(c[2]), "+f"(c[3])
                 : "r"(a0), "r"(a1), "r"(a2), "r"(a3), "r"(b0), "r"(b1));
}
__device__ __forceinline__ void ldsm4(uint32_t* r, uint32_t a) {
    asm volatile("ldmatrix.sync.aligned.m8n8.x4.shared.b16 {%0,%1,%2,%3}, [%4];"
                 : "=r"(r[0]), "=r"(r[1]), "=r"(r[2]), "=r"(r[3]) : "r"(a));
}
__device__ __forceinline__ void ldsm4t(uint32_t* r, uint32_t a) {
    asm volatile("ldmatrix.sync.aligned.m8n8.x4.trans.shared.b16 {%0,%1,%2,%3}, [%4];"
                 : "=r"(r[0]), "=r"(r[1]), "=r"(r[2]), "=r"(r[3]) : "r"(a));
}
__device__ __forceinline__ void cp16(uint32_t saddr, const void* gptr) {
    asm volatile("cp.async.cg.shared.global [%0], [%1], 16;" :: "r"(saddr), "l"(gptr));
}
#define CP_COMMIT() asm volatile("cp.async.commit_group;")
#define CP_WAIT1()  asm volatile("cp.async.wait_group 1;" ::: "memory")
#define CP_WAIT0()  asm volatile("cp.async.wait_group 0;" ::: "memory")
__device__ __forceinline__ uint32_t sptr(const void* p) {
    return (uint32_t)__cvta_generic_to_shared(p);
}
__device__ __forceinline__ uint32_t pack2(float a, float b) {
    __half2 h = __floats2half2_rn(a, b);
    return *reinterpret_cast<uint32_t*>(&h);
}
__device__ __forceinline__ float sthr(float z) {
    return (z > LAM) ? (z - LAM) : ((z < -LAM) ? (z + LAM) : 0.f);
}

// ---------------- prep ----------------
__device__ __forceinline__ float casv(int m, int k) {
    float s, c;
    sincospif((float)((m*k) & 127) * (1.0f/64.0f), &s, &c);
    return c + s;
}
__global__ void prep_kernel(const float* __restrict__ w1, const float* __restrict__ b1,
                            const float* __restrict__ w2, const float* __restrict__ b2) {
    int t = blockIdx.x * blockDim.x + threadIdx.x;
    if (t < 8*8*32) {
        int lane = t & 31, ks = (t >> 5) & 7, mt = t >> 8;
        int g = lane >> 2, tig = lane & 3;
        int m0 = mt*16 + g, k0 = ks*16 + 2*tig;
        uint4 v;
        v.x = pack2(casv(m0, k0),     casv(m0, k0+1));
        v.y = pack2(casv(m0+8, k0),   casv(m0+8, k0+1));
        v.z = pack2(casv(m0, k0+8),   casv(m0, k0+9));
        v.w = pack2(casv(m0+8, k0+8), casv(m0+8, k0+9));
        g_casPH[t] = v;
    }
    if (t < NB*BS*HID) {
        g_w1h[t] = __float2half(w1[t] + w1[NB*BS*HID + t]);
        g_w2h[t] = __float2half(w2[t] + w2[NB*HID*BS + t]);
    }
    if (t < NB*HID) g_b1s[t] = b1[t];
    if (t < NB*BS)  g_b2s[t] = b2[t];
}

extern __shared__ uint32_t smu[];

// ---------------------------------------------------------------------------
// casmul_f2h: pass 1. OUT_h = cas @ IN_f. Tile 128m x 64n x 128k.
// 8 warps, warp w owns rows [16w,16w+16) (A in regs). Register-prefetch input.
// Epilogue: smem transpose -> coalesced 16B fp16 stores. smem = 18432 B.
// ---------------------------------------------------------------------------
__global__ __launch_bounds__(256, 2)
void casmul_f2h(const float* __restrict__ in, __half* __restrict__ out,
                int ncols, int total) {
    char* bS = (char*)smu;
    const int tid = threadIdx.x;
    const int w = tid >> 5, lane = tid & 31;
    const int g = lane >> 2, tig = lane & 3;
    const int l15 = lane & 15, lc8 = (lane >> 4) * 8;
    const int ntn = ncols >> 6;

    uint4 A[8];
    #pragma unroll
    for (int ks = 0; ks < 8; ks++)
        A[ks] = __ldg(&g_casPH[(w*8 + ks)*32 + lane]);

    float4 pf[8];
    int t = blockIdx.x;
    {
        int bt = t / ntn, nb = t - bt*ntn;
        const float* src = in + (size_t)bt*128u*(size_t)ncols + nb*64;
        #pragma unroll
        for (int i = 0; i < 8; i++) {
            int idx = i*256 + tid, k = idx >> 4, n4 = (idx & 15) << 2;
            pf[i] = *(const float4*)(src + (size_t)k*(size_t)ncols + n4);
        }
    }

    for (; t < total; t += gridDim.x) {
        __syncthreads();   // prior tile fully done (MMA reads + scratch readback)
        #pragma unroll
        for (int i = 0; i < 8; i++) {
            int idx = i*256 + tid, k = idx >> 4, n4 = (idx & 15) << 2;
            uint2 u;
            u.x = pack2(pf[i].x, pf[i].y);
            u.y = pack2(pf[i].z, pf[i].w);
            *(uint2*)(bS + k*144 + n4*2) = u;
        }
        __syncthreads();

        int tn = t + gridDim.x;
        if (tn < total) {
            int bt = tn / ntn, nb = tn - bt*ntn;
            const float* src = in + (size_t)bt*128u*(size_t)ncols + nb*64;
            #pragma unroll
            for (int i = 0; i < 8; i++) {
                int idx = i*256 + tid, k = idx >> 4, n4 = (idx & 15) << 2;
                pf[i] = *(const float4*)(src + (size_t)k*(size_t)ncols + n4);
            }
        }

        float acc[8][4];
        #pragma unroll
        for (int i = 0; i < 8; i++)
            #pragma unroll
            for (int j = 0; j < 4; j++) acc[i][j] = 0.f;

        #pragma unroll
        for (int ks = 0; ks < 8; ks++) {
            #pragma unroll
            for (int nq = 0; nq < 4; nq++) {
                uint32_t b[4];
                ldsm4t(b, sptr(bS + (ks*16 + l15)*144 + (nq*16 + lc8)*2));
                mma16(acc[nq*2  ], A[ks].x, A[ks].y, A[ks].z, A[ks].w, b[0], b[1]);
                mma16(acc[nq*2+1], A[ks].x, A[ks].y, A[ks].z, A[ks].w, b[2], b[3]);
            }
        }

        __syncthreads();   // ALL warps done reading bS -> reuse as scratch
        // scratch write: row = w*16+g+r*8 (row&7 == g), swizzled 16B chunks
        #pragma unroll
        for (int nf = 0; nf < 8; nf++)
            #pragma unroll
            for (int r = 0; r < 2; r++) {
                int row = w*16 + g + r*8;
                *(uint32_t*)(bS + row*128 + ((nf ^ g) << 4) + tig*4) =
                    pack2(acc[nf][r*2], acc[nf][r*2+1]);
            }
        __syncwarp();      // warp-local rows: warp sync suffices
        {
            int bt = t / ntn, nb = t - bt*ntn;
            const size_t base = (size_t)bt*128u*(size_t)ncols + nb*64;
            #pragma unroll
            for (int i = 0; i < 4; i++) {
                int row = w*16 + (lane >> 3) + i*4;
                int q = lane & 7;
                uint4 v = *(uint4*)(bS + row*128 + ((q ^ (row & 7)) << 4));
                *(uint4*)(out + base + (size_t)row*(size_t)ncols + q*8) = v;
            }
        }
    }
}

// ---------------------------------------------------------------------------
// casmul_h2f: pass 5. OUT_f = scale*(cas @ IN_h) + add_f.
// 4m x 2n warp layout (warp tile 32m x 32n): B LDS halved vs 8m layout.
// fp16 input cp.async double-buffered. smem = 36864 B.
// ---------------------------------------------------------------------------
__global__ __launch_bounds__(256, 2)
void casmul_h2f(const __half* __restrict__ in, float* __restrict__ out,
                const float* __restrict__ addsrc, float scale, int ncols, int total) {
    char* bS0 = (char*)smu;
    char* bS1 = bS0 + 18432;
    const int tid = threadIdx.x;
    const int w = tid >> 5, lane = tid & 31;
    const int g = lane >> 2, tig = lane & 3;
    const int l15 = lane & 15, lc8 = (lane >> 4) * 8;
    const int mw = w & 3, nw = w >> 2;
    const int ntn = ncols >> 6;

    uint4 A[2][8];
    #pragma unroll
    for (int mf = 0; mf < 2; mf++)
        #pragma unroll
        for (int ks = 0; ks < 8; ks++)
            A[mf][ks] = __ldg(&g_casPH[((mw*2 + mf)*8 + ks)*32 + lane]);

    int t = blockIdx.x;
    {
        int bt = t / ntn, nb = t - bt*ntn;
        const __half* src = in + (size_t)bt*128u*(size_t)ncols + nb*64;
        #pragma unroll
        for (int i = 0; i < 4; i++) {
            int idx = i*256 + tid, k = idx >> 3, seg = idx & 7;
            cp16(sptr(bS0 + k*144 + seg*16), src + (size_t)k*(size_t)ncols + seg*8);
        }
        CP_COMMIT();
    }

    int buf = 0;
    for (; t < total; t += gridDim.x) {
        int tn = t + gridDim.x;
        if (tn < total) {
            char* bN = buf ? bS0 : bS1;
            int bt = tn / ntn, nb = tn - bt*ntn;
            const __half* src = in + (size_t)bt*128u*(size_t)ncols + nb*64;
            #pragma unroll
            for (int i = 0; i < 4; i++) {
                int idx = i*256 + tid, k = idx >> 3, seg = idx & 7;
                cp16(sptr(bN + k*144 + seg*16), src + (size_t)k*(size_t)ncols + seg*8);
            }
            CP_COMMIT();
            CP_WAIT1();
        } else {
            CP_WAIT0();
        }
        __syncthreads();

        const char* bS = buf ? bS1 : bS0;
        float acc[2][4][4];
        #pragma unroll
        for (int a = 0; a < 2; a++)
            #pragma unroll
            for (int b = 0; b < 4; b++)
                #pragma unroll
                for (int c = 0; c < 4; c++) acc[a][b][c] = 0.f;

        #pragma unroll
        for (int ks = 0; ks < 8; ks++) {
            #pragma unroll
            for (int nq = 0; nq < 2; nq++) {
                uint32_t b[4];
                ldsm4t(b, sptr(bS + (ks*16 + l15)*144 + (nw*32 + nq*16 + lc8)*2));
                #pragma unroll
                for (int mf = 0; mf < 2; mf++) {
                    mma16(acc[mf][nq*2  ], A[mf][ks].x, A[mf][ks].y, A[mf][ks].z, A[mf][ks].w, b[0], b[1]);
                    mma16(acc[mf][nq*2+1], A[mf][ks].x, A[mf][ks].y, A[mf][ks].z, A[mf][ks].w, b[2], b[3]);
                }
            }
        }

        {
            int bt = t / ntn, nb = t - bt*ntn;
            const size_t base = (size_t)bt*128u*(size_t)ncols + nb*64;
            #pragma unroll
            for (int mf = 0; mf < 2; mf++)
                #pragma unroll
                for (int nf = 0; nf < 4; nf++) {
                    int col = nw*32 + nf*8 + tig*2;
                    #pragma unroll
                    for (int r = 0; r < 2; r++) {
                        int row = mw*32 + mf*16 + g + r*8;
                        size_t o = base + (size_t)row*(size_t)ncols + col;
                        float2 v;
                        v.x = acc[mf][nf][r*2  ] * scale + addsrc[o];
                        v.y = acc[mf][nf][r*2+1] * scale + addsrc[o + 1];
                        *(float2*)&out[o] = v;
                    }
                }
        }
        __syncthreads();
        buf ^= 1;
    }
}

// ---------------------------------------------------------------------------
// fused_h: per CTA (b, wcol, blk): T = cas@X; MLP; softthresh; Z = cas@O2.
// Z epilogue now smem-transposed for coalesced fp16 stores.
// 256 threads, smem = 89088 B -> 2 CTAs/SM.
// ---------------------------------------------------------------------------
__global__ __launch_bounds__(256, 2)
void fused_h(const __half* __restrict__ in, __half* __restrict__ out) {
    char* buf = (char*)smu;                  // 34816
    char* O1  = buf + 34816;                 // 18432
    char* Wb1 = O1 + 18432;                  // 18432
    char* Wb2 = Wb1 + 18432;                 // 17408

    const int tid  = threadIdx.x;
    const int bI   = blockIdx.x >> 7;
    const int wcol = blockIdx.x & 127;
    const int blk  = blockIdx.y;
    const size_t gbase = ((size_t)(bI*128)*128u + (size_t)wcol)*1024u + (size_t)blk*128u;

    #pragma unroll
    for (int i = 0; i < 8; i++) {
        int idx = i*256 + tid, h = idx >> 4, seg = idx & 15;
        cp16(sptr(buf + h*272 + seg*16), in + gbase + (size_t)h*131072u + seg*8);
    }
    CP_COMMIT(); CP_WAIT0();

    const int wid = tid >> 5, lane = tid & 31;
    const int g = lane >> 2, tig = lane & 3;
    const int mw = wid & 3, nw = wid >> 2;
    const int l15 = lane & 15, lc8 = (lane >> 4) * 8;
    const int m0 = mw*32;
    __syncthreads();

    {   // T = cas @ X
        float acc[2][8][4];
        #pragma unroll
        for (int a = 0; a < 2; a++) for (int b = 0; b < 8; b++) for (int c = 0; c < 4; c++) acc[a][b][c] = 0.f;
        #pragma unroll
        for (int ks = 0; ks < 8; ks++) {
            uint4 A0 = __ldg(&g_casPH[((mw*2  )*8 + ks)*32 + lane]);
            uint4 A1 = __ldg(&g_casPH[((mw*2+1)*8 + ks)*32 + lane]);
            #pragma unroll
            for (int nq = 0; nq < 4; nq++) {
                uint32_t b[4];
                ldsm4t(b, sptr(buf + (ks*16 + l15)*272 + (nw*64 + nq*16 + lc8)*2));
                mma16(acc[0][nq*2  ], A0.x, A0.y, A0.z, A0.w, b[0], b[1]);
                mma16(acc[0][nq*2+1], A0.x, A0.y, A0.z, A0.w, b[2], b[3]);
                mma16(acc[1][nq*2  ], A1.x, A1.y, A1.z, A1.w, b[0], b[1]);
                mma16(acc[1][nq*2+1], A1.x, A1.y, A1.z, A1.w, b[2], b[3]);
            }
        }
        __syncthreads();
        #pragma unroll
        for (int mf = 0; mf < 2; mf++) for (int nf = 0; nf < 8; nf++) {
            int n = nw*64 + nf*8 + tig*2;
            #pragma unroll
            for (int r = 0; r < 2; r++) {
                int m = m0 + mf*16 + g + r*8;
                *(uint32_t*)(buf + m*272 + n*2) = pack2(acc[mf][nf][r*2], acc[mf][nf][r*2+1]);
            }
        }
        __syncthreads();
    }

    const __half* W1 = g_w1h + blk*BS*HID;
    const __half* W2 = g_w2h + blk*HID*BS;

    float acc2[2][8][4];
    #pragma unroll
    for (int a = 0; a < 2; a++) for (int b = 0; b < 8; b++) for (int c = 0; c < 4; c++) acc2[a][b][c] = 0.f;

    for (int ch = 0; ch < 4; ch++) {
        #pragma unroll
        for (int i = 0; i < 4; i++) {
            int idx = i*256 + tid, k = idx >> 3, seg = idx & 7;
            cp16(sptr(Wb1 + k*144 + seg*16), W1 + k*HID + ch*64 + seg*8);
        }
        #pragma unroll
        for (int i = 0; i < 4; i++) {
            int idx = i*256 + tid, k = idx >> 4, seg = idx & 15;
            cp16(sptr(Wb2 + k*272 + seg*16), W2 + (size_t)(ch*64 + k)*BS + seg*8);
        }
        CP_COMMIT(); CP_WAIT0(); __syncthreads();

        float acc1[2][4][4];
        #pragma unroll
        for (int a = 0; a < 2; a++) for (int b = 0; b < 4; b++) for (int c = 0; c < 4; c++) acc1[a][b][c] = 0.f;

        #pragma unroll
        for (int ks = 0; ks < 8; ks++) {
            uint32_t a0[4], a1[4];
            ldsm4(a0, sptr(buf + (m0      + l15)*272 + (ks*16 + lc8)*2));
            ldsm4(a1, sptr(buf + (m0 + 16 + l15)*272 + (ks*16 + lc8)*2));
            #pragma unroll
            for (int nq = 0; nq < 2; nq++) {
                uint32_t b[4];
                ldsm4t(b, sptr(Wb1 + (ks*16 + l15)*144 + (nw*32 + nq*16 + lc8)*2));
                mma16(acc1[0][nq*2  ], a0[0], a0[1], a0[2], a0[3], b[0], b[1]);
                mma16(acc1[0][nq*2+1], a0[0], a0[1], a0[2], a0[3], b[2], b[3]);
                mma16(acc1[1][nq*2  ], a1[0], a1[1], a1[2], a1[3], b[0], b[1]);
                mma16(acc1[1][nq*2+1], a1[0], a1[1], a1[2], a1[3], b[2], b[3]);
            }
        }

        #pragma unroll
        for (int mf = 0; mf < 2; mf++) for (int nf = 0; nf < 4; nf++) {
            int nc = nw*32 + nf*8 + tig*2;
            float bx = g_b1s[blk*HID + ch*64 + nc];
            float by = g_b1s[blk*HID + ch*64 + nc + 1];
            #pragma unroll
            for (int r = 0; r < 2; r++) {
                int m = m0 + mf*16 + g + r*8;
                *(uint32_t*)(O1 + m*144 + nc*2) =
                    pack2(fmaxf(acc1[mf][nf][r*2] + bx, 0.f), fmaxf(acc1[mf][nf][r*2+1] + by, 0.f));
            }
        }
        __syncthreads();

        #pragma unroll
        for (int ks = 0; ks < 4; ks++) {
            uint32_t a0[4], a1[4];
            ldsm4(a0, sptr(O1 + (m0      + l15)*144 + (ks*16 + lc8)*2));
            ldsm4(a1, sptr(O1 + (m0 + 16 + l15)*144 + (ks*16 + lc8)*2));
            #pragma unroll
            for (int nq = 0; nq < 4; nq++) {
                uint32_t b[4];
                ldsm4t(b, sptr(Wb2 + (ks*16 + l15)*272 + (nw*64 + nq*16 + lc8)*2));
                mma16(acc2[0][nq*2  ], a0[0], a0[1], a0[2], a0[3], b[0], b[1]);
                mma16(acc2[0][nq*2+1], a0[0], a0[1], a0[2], a0[3], b[2], b[3]);
                mma16(acc2[1][nq*2  ], a1[0], a1[1], a1[2], a1[3], b[0], b[1]);
                mma16(acc2[1][nq*2+1], a1[0], a1[1], a1[2], a1[3], b[2], b[3]);
            }
        }
        __syncthreads();
    }

    #pragma unroll
    for (int mf = 0; mf < 2; mf++) for (int nf = 0; nf < 8; nf++) {
        int n = nw*64 + nf*8 + tig*2;
        float bx = g_b2s[blk*BS + n], by = g_b2s[blk*BS + n + 1];
        #pragma unroll
        for (int r = 0; r < 2; r++) {
            int m = m0 + mf*16 + g + r*8;
            *(uint32_t*)(buf + m*272 + n*2) =
                pack2(sthr(acc2[mf][nf][r*2] + bx), sthr(acc2[mf][nf][r*2+1] + by));
        }
    }
    __syncthreads();

    {   // Z = cas @ O2
        float acc[2][8][4];
        #pragma unroll
        for (int a = 0; a < 2; a++) for (int b = 0; b < 8; b++) for (int c = 0; c < 4; c++) acc[a][b][c] = 0.f;
        #pragma unroll
        for (int ks = 0; ks < 8; ks++) {
            uint4 A0 = __ldg(&g_casPH[((mw*2  )*8 + ks)*32 + lane]);
            uint4 A1 = __ldg(&g_casPH[((mw*2+1)*8 + ks)*32 + lane]);
            #pragma unroll
            for (int nq = 0; nq < 4; nq++) {
                uint32_t b[4];
                ldsm4t(b, sptr(buf + (ks*16 + l15)*272 + (nw*64 + nq*16 + lc8)*2));
                mma16(acc[0][nq*2  ], A0.x, A0.y, A0.z, A0.w, b[0], b[1]);
                mma16(acc[0][nq*2+1], A0.x, A0.y, A0.z, A0.w, b[2], b[3]);
                mma16(acc[1][nq*2  ], A1.x, A1.y, A1.z, A1.w, b[0], b[1]);
                mma16(acc[1][nq*2+1], A1.x, A1.y, A1.z, A1.w, b[2], b[3]);
            }
        }

        __syncthreads();   // all Z reads of buf done -> reuse buf as scratch (pitch 256B)
        #pragma unroll
        for (int mf = 0; mf < 2; mf++) for (int nf = 0; nf < 8; nf++) {
            #pragma unroll
            for (int r = 0; r < 2; r++) {
                int m = m0 + mf*16 + g + r*8;   // m&7 == g
                *(uint32_t*)(buf + m*256 + (((nw << 3) | (nf ^ g)) << 4) + tig*4) =
                    pack2(acc[mf][nf][r*2], acc[mf][nf][r*2+1]);
            }
        }
        __syncthreads();   // cross-warp: readers consume both nw halves of each row
        #pragma unroll
        for (int pass = 0; pass < 8; pass++) {
            int row = pass*16 + (tid >> 4);
            int q = tid & 15;
            int ch = (q & 8) | ((q & 7) ^ (row & 7));
            uint4 v = *(uint4*)(buf + row*256 + ch*16);
            *(uint4*)(out + gbase + (size_t)row*131072u + q*8) = v;
        }
    }
}

// ---------------------------------------------------------------------------
extern "C" void kernel_launch(void* const* d_in, const int* in_sizes, int n_in,
                              void* d_out, int out_size) {
    const float* x  = (const float*)d_in[0];
    const float* w1 = (const float*)d_in[1];
    const float* b1 = (const float*)d_in[2];
    const float* w2 = (const float*)d_in[3];
    const float* b2 = (const float*)d_in[4];
    float* out = (float*)d_out;

    void *p1, *p2;
    cudaGetSymbolAddress(&p1, g_bh1);
    cudaGetSymbolAddress(&p2, g_bh2);
    __half* bh1 = (__half*)p1;
    __half* bh2 = (__half*)p2;

    const int CAS1_SMEM = 18432;
    const int CAS2_SMEM = 36864;
    const int MID_SMEM  = 34816 + 18432 + 18432 + 17408;   // 89088
    cudaFuncSetAttribute(casmul_f2h, cudaFuncAttributeMaxDynamicSharedMemorySize, CAS1_SMEM);
    cudaFuncSetAttribute(casmul_h2f, cudaFuncAttributeMaxDynamicSharedMemorySize, CAS2_SMEM);
    cudaFuncSetAttribute(fused_h,    cudaFuncAttributeMaxDynamicSharedMemorySize, MID_SMEM);

    prep_kernel<<<1024, 256>>>(w1, b1, w2, b2);

    const int GRID = 296;
    const int T1 = (CC/64) * (BB*HH);      // 8192 tiles

    casmul_f2h<<<GRID, 256, CAS1_SMEM>>>(x, bh1, CC, T1);
    fused_h<<<dim3(BB*WW, NB), 256, MID_SMEM>>>(bh1, bh2);
    casmul_h2f<<<GRID, 256, CAS2_SMEM>>>(bh2, out, x, 1.0f/(HH*WW), CC, T1);
}

// round 12
// speedup vs baseline: 2.4893x; 1.1381x over previous
#include <cuda_runtime.h>
#include <cuda_fp16.h>
#include <stdint.h>

#define BB 4
#define HH 128
#define WW 128
#define CC 1024
#define NB 8
#define BS 128
#define HID 256
#define LAM 0.01f
#define NTOT (BB*HH*WW*CC)

__device__ __align__(128) __half g_bh1[NTOT];
__device__ __align__(128) __half g_bh2[NTOT];
__device__ __align__(16) uint4 g_casPH[8*8*32];   // m16n8k16 A-fragment layout
__device__ __align__(16) __half g_w1h[NB*BS*HID];
__device__ __align__(16) __half g_w2h[NB*HID*BS];
__device__ float g_b1s[NB*HID];
__device__ float g_b2s[NB*BS];

// ---------------- helpers ----------------
__device__ __forceinline__ void mma16(float* c, uint32_t a0, uint32_t a1, uint32_t a2, uint32_t a3,
                                      uint32_t b0, uint32_t b1) {
    asm volatile("mma.sync.aligned.m16n8k16.row.col.f32.f16.f16.f32 "
                 "{%0,%1,%2,%3}, {%4,%5,%6,%7}, {%8,%9}, {%0,%1,%2,%3};"
                 : "+f"(c[0]), "+f"(c[1]), "+f"(c[2]), "+f"(c[3])
                 : "r"(a0), "r"(a1), "r"(a2), "r"(a3), "r"(b0), "r"(b1));
}
__device__ __forceinline__ void ldsm4(uint32_t* r, uint32_t a) {
    asm volatile("ldmatrix.sync.aligned.m8n8.x4.shared.b16 {%0,%1,%2,%3}, [%4];"
                 : "=r"(r[0]), "=r"(r[1]), "=r"(r[2]), "=r"(r[3]) : "r"(a));
}
__device__ __forceinline__ void ldsm4t(uint32_t* r, uint32_t a) {
    asm volatile("ldmatrix.sync.aligned.m8n8.x4.trans.shared.b16 {%0,%1,%2,%3}, [%4];"
                 : "=r"(r[0]), "=r"(r[1]), "=r"(r[2]), "=r"(r[3]) : "r"(a));
}
__device__ __forceinline__ void cp16(uint32_t saddr, const void* gptr) {
    asm volatile("cp.async.cg.shared.global [%0], [%1], 16;" :: "r"(saddr), "l"(gptr));
}
#define CP_COMMIT() asm volatile("cp.async.commit_group;")
#define CP_WAIT1()  asm volatile("cp.async.wait_group 1;" ::: "memory")
#define CP_WAIT0()  asm volatile("cp.async.wait_group 0;" ::: "memory")
__device__ __forceinline__ uint32_t sptr(const void* p) {
    return (uint32_t)__cvta_generic_to_shared(p);
}
__device__ __forceinline__ uint32_t pack2(float a, float b) {
    __half2 h = __floats2half2_rn(a, b);
    return *reinterpret_cast<uint32_t*>(&h);
}
__device__ __forceinline__ float sthr(float z) {
    return (z > LAM) ? (z - LAM) : ((z < -LAM) ? (z + LAM) : 0.f);
}

// ---------------- prep ----------------
__device__ __forceinline__ float casv(int m, int k) {
    float s, c;
    sincospif((float)((m*k) & 127) * (1.0f/64.0f), &s, &c);
    return c + s;
}
__global__ void prep_kernel(const float* __restrict__ w1, const float* __restrict__ b1,
                            const float* __restrict__ w2, const float* __restrict__ b2) {
    int t = blockIdx.x * blockDim.x + threadIdx.x;
    if (t < 8*8*32) {
        int lane = t & 31, ks = (t >> 5) & 7, mt = t >> 8;
        int g = lane >> 2, tig = lane & 3;
        int m0 = mt*16 + g, k0 = ks*16 + 2*tig;
        uint4 v;
        v.x = pack2(casv(m0, k0),     casv(m0, k0+1));
        v.y = pack2(casv(m0+8, k0),   casv(m0+8, k0+1));
        v.z = pack2(casv(m0, k0+8),   casv(m0, k0+9));
        v.w = pack2(casv(m0+8, k0+8), casv(m0+8, k0+9));
        g_casPH[t] = v;
    }
    if (t < NB*BS*HID) {
        g_w1h[t] = __float2half(w1[t] + w1[NB*BS*HID + t]);
        g_w2h[t] = __float2half(w2[t] + w2[NB*HID*BS + t]);
    }
    if (t < NB*HID) g_b1s[t] = b1[t];
    if (t < NB*BS)  g_b2s[t] = b2[t];
}

extern __shared__ uint32_t smu[];

// ---------------------------------------------------------------------------
// casmul_f2h: pass 1 (unchanged from round 11). OUT_h = cas @ IN_f.
// 8 warps, A in regs; register-prefetch input; smem-transpose epilogue.
// smem = 18432 B.
// ---------------------------------------------------------------------------
__global__ __launch_bounds__(256, 2)
void casmul_f2h(const float* __restrict__ in, __half* __restrict__ out,
                int ncols, int total) {
    char* bS = (char*)smu;
    const int tid = threadIdx.x;
    const int w = tid >> 5, lane = tid & 31;
    const int g = lane >> 2, tig = lane & 3;
    const int l15 = lane & 15, lc8 = (lane >> 4) * 8;
    const int ntn = ncols >> 6;

    uint4 A[8];
    #pragma unroll
    for (int ks = 0; ks < 8; ks++)
        A[ks] = __ldg(&g_casPH[(w*8 + ks)*32 + lane]);

    float4 pf[8];
    int t = blockIdx.x;
    {
        int bt = t / ntn, nb = t - bt*ntn;
        const float* src = in + (size_t)bt*128u*(size_t)ncols + nb*64;
        #pragma unroll
        for (int i = 0; i < 8; i++) {
            int idx = i*256 + tid, k = idx >> 4, n4 = (idx & 15) << 2;
            pf[i] = *(const float4*)(src + (size_t)k*(size_t)ncols + n4);
        }
    }

    for (; t < total; t += gridDim.x) {
        __syncthreads();
        #pragma unroll
        for (int i = 0; i < 8; i++) {
            int idx = i*256 + tid, k = idx >> 4, n4 = (idx & 15) << 2;
            uint2 u;
            u.x = pack2(pf[i].x, pf[i].y);
            u.y = pack2(pf[i].z, pf[i].w);
            *(uint2*)(bS + k*144 + n4*2) = u;
        }
        __syncthreads();

        int tn = t + gridDim.x;
        if (tn < total) {
            int bt = tn / ntn, nb = tn - bt*ntn;
            const float* src = in + (size_t)bt*128u*(size_t)ncols + nb*64;
            #pragma unroll
            for (int i = 0; i < 8; i++) {
                int idx = i*256 + tid, k = idx >> 4, n4 = (idx & 15) << 2;
                pf[i] = *(const float4*)(src + (size_t)k*(size_t)ncols + n4);
            }
        }

        float acc[8][4];
        #pragma unroll
        for (int i = 0; i < 8; i++)
            #pragma unroll
            for (int j = 0; j < 4; j++) acc[i][j] = 0.f;

        #pragma unroll
        for (int ks = 0; ks < 8; ks++) {
            #pragma unroll
            for (int nq = 0; nq < 4; nq++) {
                uint32_t b[4];
                ldsm4t(b, sptr(bS + (ks*16 + l15)*144 + (nq*16 + lc8)*2));
                mma16(acc[nq*2  ], A[ks].x, A[ks].y, A[ks].z, A[ks].w, b[0], b[1]);
                mma16(acc[nq*2+1], A[ks].x, A[ks].y, A[ks].z, A[ks].w, b[2], b[3]);
            }
        }

        __syncthreads();
        #pragma unroll
        for (int nf = 0; nf < 8; nf++)
            #pragma unroll
            for (int r = 0; r < 2; r++) {
                int row = w*16 + g + r*8;
                *(uint32_t*)(bS + row*128 + ((nf ^ g) << 4) + tig*4) =
                    pack2(acc[nf][r*2], acc[nf][r*2+1]);
            }
        __syncwarp();
        {
            int bt = t / ntn, nb = t - bt*ntn;
            const size_t base = (size_t)bt*128u*(size_t)ncols + nb*64;
            #pragma unroll
            for (int i = 0; i < 4; i++) {
                int row = w*16 + (lane >> 3) + i*4;
                int q = lane & 7;
                uint4 v = *(uint4*)(bS + row*128 + ((q ^ (row & 7)) << 4));
                *(uint4*)(out + base + (size_t)row*(size_t)ncols + q*8) = v;
            }
        }
    }
}

// ---------------------------------------------------------------------------
// casmul_h2f: pass 5. OUT_f = scale*(cas @ IN_h) + add_f.
// 4m x 2n warps. B AND residual cp.async double-buffered (one commit group):
// epilogue has zero gmem-load latency. smem = 2*18432 + 2*34816 = 106496 B.
// Residual pitch 272 B (68 fl): row stride = 4 banks -> conflict-free g-spread.
// ---------------------------------------------------------------------------
__global__ __launch_bounds__(256, 2)
void casmul_h2f(const __half* __restrict__ in, float* __restrict__ out,
                const float* __restrict__ addsrc, float scale, int ncols, int total) {
    char* bS0 = (char*)smu;
    char* bS1 = bS0 + 18432;
    char* rS0 = bS1 + 18432;      // fp32 [128][68pitch] = 34816 B
    char* rS1 = rS0 + 34816;
    const int tid = threadIdx.x;
    const int w = tid >> 5, lane = tid & 31;
    const int g = lane >> 2, tig = lane & 3;
    const int l15 = lane & 15, lc8 = (lane >> 4) * 8;
    const int mw = w & 3, nw = w >> 2;
    const int ntn = ncols >> 6;

    uint4 A[2][8];
    #pragma unroll
    for (int mf = 0; mf < 2; mf++)
        #pragma unroll
        for (int ks = 0; ks < 8; ks++)
            A[mf][ks] = __ldg(&g_casPH[((mw*2 + mf)*8 + ks)*32 + lane]);

    int t = blockIdx.x;
    {
        int bt = t / ntn, nb = t - bt*ntn;
        const size_t base = (size_t)bt*128u*(size_t)ncols + nb*64;
        const __half* src = in + base;
        #pragma unroll
        for (int i = 0; i < 4; i++) {
            int idx = i*256 + tid, k = idx >> 3, seg = idx & 7;
            cp16(sptr(bS0 + k*144 + seg*16), src + (size_t)k*(size_t)ncols + seg*8);
        }
        const float* rsrc = addsrc + base;
        #pragma unroll
        for (int i = 0; i < 8; i++) {
            int idx = i*256 + tid, k = idx >> 4, seg = idx & 15;
            cp16(sptr(rS0 + k*272 + seg*16), rsrc + (size_t)k*(size_t)ncols + seg*4);
        }
        CP_COMMIT();
    }

    int buf = 0;
    for (; t < total; t += gridDim.x) {
        int tn = t + gridDim.x;
        if (tn < total) {
            char* bN = buf ? bS0 : bS1;
            char* rN = buf ? rS0 : rS1;
            int bt = tn / ntn, nb = tn - bt*ntn;
            const size_t base = (size_t)bt*128u*(size_t)ncols + nb*64;
            const __half* src = in + base;
            #pragma unroll
            for (int i = 0; i < 4; i++) {
                int idx = i*256 + tid, k = idx >> 3, seg = idx & 7;
                cp16(sptr(bN + k*144 + seg*16), src + (size_t)k*(size_t)ncols + seg*8);
            }
            const float* rsrc = addsrc + base;
            #pragma unroll
            for (int i = 0; i < 8; i++) {
                int idx = i*256 + tid, k = idx >> 4, seg = idx & 15;
                cp16(sptr(rN + k*272 + seg*16), rsrc + (size_t)k*(size_t)ncols + seg*4);
            }
            CP_COMMIT();
            CP_WAIT1();
        } else {
            CP_WAIT0();
        }
        __syncthreads();

        const char* bS = buf ? bS1 : bS0;
        const char* rS = buf ? rS1 : rS0;
        float acc[2][4][4];
        #pragma unroll
        for (int a = 0; a < 2; a++)
            #pragma unroll
            for (int b = 0; b < 4; b++)
                #pragma unroll
                for (int c = 0; c < 4; c++) acc[a][b][c] = 0.f;

        #pragma unroll
        for (int ks = 0; ks < 8; ks++) {
            #pragma unroll
            for (int nq = 0; nq < 2; nq++) {
                uint32_t b[4];
                ldsm4t(b, sptr(bS + (ks*16 + l15)*144 + (nw*32 + nq*16 + lc8)*2));
                #pragma unroll
                for (int mf = 0; mf < 2; mf++) {
                    mma16(acc[mf][nq*2  ], A[mf][ks].x, A[mf][ks].y, A[mf][ks].z, A[mf][ks].w, b[0], b[1]);
                    mma16(acc[mf][nq*2+1], A[mf][ks].x, A[mf][ks].y, A[mf][ks].z, A[mf][ks].w, b[2], b[3]);
                }
            }
        }

        {
            int bt = t / ntn, nb = t - bt*ntn;
            const size_t base = (size_t)bt*128u*(size_t)ncols + nb*64;
            #pragma unroll
            for (int mf = 0; mf < 2; mf++)
                #pragma unroll
                for (int nf = 0; nf < 4; nf++) {
                    int col = nw*32 + nf*8 + tig*2;
                    #pragma unroll
                    for (int r = 0; r < 2; r++) {
                        int row = mw*32 + mf*16 + g + r*8;
                        float2 rr = *(const float2*)(rS + row*272 + col*4);
                        float2 v;
                        v.x = acc[mf][nf][r*2  ] * scale + rr.x;
                        v.y = acc[mf][nf][r*2+1] * scale + rr.y;
                        *(float2*)&out[base + (size_t)row*(size_t)ncols + col] = v;
                    }
                }
        }
        __syncthreads();
        buf ^= 1;
    }
}

// ---------------------------------------------------------------------------
// fused_h: T = cas@X; MLP; softthresh; Z = cas@O2 (smem-transpose epilogue).
// Chunk-0 weights prefetched concurrently with X load (separate cp group).
// 256 threads, smem = 89088 B -> 2 CTAs/SM.
// ---------------------------------------------------------------------------
__global__ __launch_bounds__(256, 2)
void fused_h(const __half* __restrict__ in, __half* __restrict__ out) {
    char* buf = (char*)smu;                  // 34816
    char* O1  = buf + 34816;                 // 18432
    char* Wb1 = O1 + 18432;                  // 18432
    char* Wb2 = Wb1 + 18432;                 // 17408

    const int tid  = threadIdx.x;
    const int bI   = blockIdx.x >> 7;
    const int wcol = blockIdx.x & 127;
    const int blk  = blockIdx.y;
    const size_t gbase = ((size_t)(bI*128)*128u + (size_t)wcol)*1024u + (size_t)blk*128u;

    const __half* W1 = g_w1h + blk*BS*HID;
    const __half* W2 = g_w2h + blk*HID*BS;

    // group 0: X tile
    #pragma unroll
    for (int i = 0; i < 8; i++) {
        int idx = i*256 + tid, h = idx >> 4, seg = idx & 15;
        cp16(sptr(buf + h*272 + seg*16), in + gbase + (size_t)h*131072u + seg*8);
    }
    CP_COMMIT();
    // group 1: chunk-0 weights (awaited at GEMM1 of ch=0)
    #pragma unroll
    for (int i = 0; i < 4; i++) {
        int idx = i*256 + tid, k = idx >> 3, seg = idx & 7;
        cp16(sptr(Wb1 + k*144 + seg*16), W1 + k*HID + seg*8);
    }
    #pragma unroll
    for (int i = 0; i < 4; i++) {
        int idx = i*256 + tid, k = idx >> 4, seg = idx & 15;
        cp16(sptr(Wb2 + k*272 + seg*16), W2 + (size_t)k*BS + seg*8);
    }
    CP_COMMIT();
    CP_WAIT1();   // X ready; weights still in flight

    const int wid = tid >> 5, lane = tid & 31;
    const int g = lane >> 2, tig = lane & 3;
    const int mw = wid & 3, nw = wid >> 2;
    const int l15 = lane & 15, lc8 = (lane >> 4) * 8;
    const int m0 = mw*32;
    __syncthreads();

    {   // T = cas @ X
        float acc[2][8][4];
        #pragma unroll
        for (int a = 0; a < 2; a++) for (int b = 0; b < 8; b++) for (int c = 0; c < 4; c++) acc[a][b][c] = 0.f;
        #pragma unroll
        for (int ks = 0; ks < 8; ks++) {
            uint4 A0 = __ldg(&g_casPH[((mw*2  )*8 + ks)*32 + lane]);
            uint4 A1 = __ldg(&g_casPH[((mw*2+1)*8 + ks)*32 + lane]);
            #pragma unroll
            for (int nq = 0; nq < 4; nq++) {
                uint32_t b[4];
                ldsm4t(b, sptr(buf + (ks*16 + l15)*272 + (nw*64 + nq*16 + lc8)*2));
                mma16(acc[0][nq*2  ], A0.x, A0.y, A0.z, A0.w, b[0], b[1]);
                mma16(acc[0][nq*2+1], A0.x, A0.y, A0.z, A0.w, b[2], b[3]);
                mma16(acc[1][nq*2  ], A1.x, A1.y, A1.z, A1.w, b[0], b[1]);
                mma16(acc[1][nq*2+1], A1.x, A1.y, A1.z, A1.w, b[2], b[3]);
            }
        }
        __syncthreads();
        #pragma unroll
        for (int mf = 0; mf < 2; mf++) for (int nf = 0; nf < 8; nf++) {
            int n = nw*64 + nf*8 + tig*2;
            #pragma unroll
            for (int r = 0; r < 2; r++) {
                int m = m0 + mf*16 + g + r*8;
                *(uint32_t*)(buf + m*272 + n*2) = pack2(acc[mf][nf][r*2], acc[mf][nf][r*2+1]);
            }
        }
        __syncthreads();
    }

    float acc2[2][8][4];
    #pragma unroll
    for (int a = 0; a < 2; a++) for (int b = 0; b < 8; b++) for (int c = 0; c < 4; c++) acc2[a][b][c] = 0.f;

    for (int ch = 0; ch < 4; ch++) {
        if (ch > 0) {
            #pragma unroll
            for (int i = 0; i < 4; i++) {
                int idx = i*256 + tid, k = idx >> 3, seg = idx & 7;
                cp16(sptr(Wb1 + k*144 + seg*16), W1 + k*HID + ch*64 + seg*8);
            }
            #pragma unroll
            for (int i = 0; i < 4; i++) {
                int idx = i*256 + tid, k = idx >> 4, seg = idx & 15;
                cp16(sptr(Wb2 + k*272 + seg*16), W2 + (size_t)(ch*64 + k)*BS + seg*8);
            }
            CP_COMMIT();
        }
        CP_WAIT0(); __syncthreads();

        float acc1[2][4][4];
        #pragma unroll
        for (int a = 0; a < 2; a++) for (int b = 0; b < 4; b++) for (int c = 0; c < 4; c++) acc1[a][b][c] = 0.f;

        #pragma unroll
        for (int ks = 0; ks < 8; ks++) {
            uint32_t a0[4], a1[4];
            ldsm4(a0, sptr(buf + (m0      + l15)*272 + (ks*16 + lc8)*2));
            ldsm4(a1, sptr(buf + (m0 + 16 + l15)*272 + (ks*16 + lc8)*2));
            #pragma unroll
            for (int nq = 0; nq < 2; nq++) {
                uint32_t b[4];
                ldsm4t(b, sptr(Wb1 + (ks*16 + l15)*144 + (nw*32 + nq*16 + lc8)*2));
                mma16(acc1[0][nq*2  ], a0[0], a0[1], a0[2], a0[3], b[0], b[1]);
                mma16(acc1[0][nq*2+1], a0[0], a0[1], a0[2], a0[3], b[2], b[3]);
                mma16(acc1[1][nq*2  ], a1[0], a1[1], a1[2], a1[3], b[0], b[1]);
                mma16(acc1[1][nq*2+1], a1[0], a1[1], a1[2], a1[3], b[2], b[3]);
            }
        }

        #pragma unroll
        for (int mf = 0; mf < 2; mf++) for (int nf = 0; nf < 4; nf++) {
            int nc = nw*32 + nf*8 + tig*2;
            float bx = g_b1s[blk*HID + ch*64 + nc];
            float by = g_b1s[blk*HID + ch*64 + nc + 1];
            #pragma unroll
            for (int r = 0; r < 2; r++) {
                int m = m0 + mf*16 + g + r*8;
                *(uint32_t*)(O1 + m*144 + nc*2) =
                    pack2(fmaxf(acc1[mf][nf][r*2] + bx, 0.f), fmaxf(acc1[mf][nf][r*2+1] + by, 0.f));
            }
        }
        __syncthreads();

        #pragma unroll
        for (int ks = 0; ks < 4; ks++) {
            uint32_t a0[4], a1[4];
            ldsm4(a0, sptr(O1 + (m0      + l15)*144 + (ks*16 + lc8)*2));
            ldsm4(a1, sptr(O1 + (m0 + 16 + l15)*144 + (ks*16 + lc8)*2));
            #pragma unroll
            for (int nq = 0; nq < 4; nq++) {
                uint32_t b[4];
                ldsm4t(b, sptr(Wb2 + (ks*16 + l15)*272 + (nw*64 + nq*16 + lc8)*2));
                mma16(acc2[0][nq*2  ], a0[0], a0[1], a0[2], a0[3], b[0], b[1]);
                mma16(acc2[0][nq*2+1], a0[0], a0[1], a0[2], a0[3], b[2], b[3]);
                mma16(acc2[1][nq*2  ], a1[0], a1[1], a1[2], a1[3], b[0], b[1]);
                mma16(acc2[1][nq*2+1], a1[0], a1[1], a1[2], a1[3], b[2], b[3]);
            }
        }
        __syncthreads();   // Wb/O1 reads done before next chunk restage
    }

    #pragma unroll
    for (int mf = 0; mf < 2; mf++) for (int nf = 0; nf < 8; nf++) {
        int n = nw*64 + nf*8 + tig*2;
        float bx = g_b2s[blk*BS + n], by = g_b2s[blk*BS + n + 1];
        #pragma unroll
        for (int r = 0; r < 2; r++) {
            int m = m0 + mf*16 + g + r*8;
            *(uint32_t*)(buf + m*272 + n*2) =
                pack2(sthr(acc2[mf][nf][r*2] + bx), sthr(acc2[mf][nf][r*2+1] + by));
        }
    }
    __syncthreads();

    {   // Z = cas @ O2
        float acc[2][8][4];
        #pragma unroll
        for (int a = 0; a < 2; a++) for (int b = 0; b < 8; b++) for (int c = 0; c < 4; c++) acc[a][b][c] = 0.f;
        #pragma unroll
        for (int ks = 0; ks < 8; ks++) {
            uint4 A0 = __ldg(&g_casPH[((mw*2  )*8 + ks)*32 + lane]);
            uint4 A1 = __ldg(&g_casPH[((mw*2+1)*8 + ks)*32 + lane]);
            #pragma unroll
            for (int nq = 0; nq < 4; nq++) {
                uint32_t b[4];
                ldsm4t(b, sptr(buf + (ks*16 + l15)*272 + (nw*64 + nq*16 + lc8)*2));
                mma16(acc[0][nq*2  ], A0.x, A0.y, A0.z, A0.w, b[0], b[1]);
                mma16(acc[0][nq*2+1], A0.x, A0.y, A0.z, A0.w, b[2], b[3]);
                mma16(acc[1][nq*2  ], A1.x, A1.y, A1.z, A1.w, b[0], b[1]);
                mma16(acc[1][nq*2+1], A1.x, A1.y, A1.z, A1.w, b[2], b[3]);
            }
        }

        __syncthreads();   // all Z reads of buf done -> reuse buf as scratch (pitch 256B)
        #pragma unroll
        for (int mf = 0; mf < 2; mf++) for (int nf = 0; nf < 8; nf++) {
            #pragma unroll
            for (int r = 0; r < 2; r++) {
                int m = m0 + mf*16 + g + r*8;   // m&7 == g
                *(uint32_t*)(buf + m*256 + (((nw << 3) | (nf ^ g)) << 4) + tig*4) =
                    pack2(acc[mf][nf][r*2], acc[mf][nf][r*2+1]);
            }
        }
        __syncthreads();
        #pragma unroll
        for (int pass = 0; pass < 8; pass++) {
            int row = pass*16 + (tid >> 4);
            int q = tid & 15;
            int ch = (q & 8) | ((q & 7) ^ (row & 7));
            uint4 v = *(uint4*)(buf + row*256 + ch*16);
            *(uint4*)(out + gbase + (size_t)row*131072u + q*8) = v;
        }
    }
}

// ---------------------------------------------------------------------------
extern "C" void kernel_launch(void* const* d_in, const int* in_sizes, int n_in,
                              void* d_out, int out_size) {
    const float* x  = (const float*)d_in[0];
    const float* w1 = (const float*)d_in[1];
    const float* b1 = (const float*)d_in[2];
    const float* w2 = (const float*)d_in[3];
    const float* b2 = (const float*)d_in[4];
    float* out = (float*)d_out;

    void *p1, *p2;
    cudaGetSymbolAddress(&p1, g_bh1);
    cudaGetSymbolAddress(&p2, g_bh2);
    __half* bh1 = (__half*)p1;
    __half* bh2 = (__half*)p2;

    const int CAS1_SMEM = 18432;
    const int CAS2_SMEM = 2*18432 + 2*34816;               // 106496
    const int MID_SMEM  = 34816 + 18432 + 18432 + 17408;   // 89088
    cudaFuncSetAttribute(casmul_f2h, cudaFuncAttributeMaxDynamicSharedMemorySize, CAS1_SMEM);
    cudaFuncSetAttribute(casmul_h2f, cudaFuncAttributeMaxDynamicSharedMemorySize, CAS2_SMEM);
    cudaFuncSetAttribute(fused_h,    cudaFuncAttributeMaxDynamicSharedMemorySize, MID_SMEM);

    prep_kernel<<<1024, 256>>>(w1, b1, w2, b2);

    const int GRID = 296;
    const int T1 = (CC/64) * (BB*HH);      // 8192 tiles

    casmul_f2h<<<GRID, 256, CAS1_SMEM>>>(x, bh1, CC, T1);
    fused_h<<<dim3(BB*WW, NB), 256, MID_SMEM>>>(bh1, bh2);
    casmul_h2f<<<GRID, 256, CAS2_SMEM>>>(bh2, out, x, 1.0f/(HH*WW), CC, T1);
}